// round 15
// baseline (speedup 1.0000x reference)
#include <cuda_runtime.h>
#include <cuda_fp16.h>
#include <math.h>

#define NN 50000
#define NE 800000
#define NTILES 6250
#define NODE_TILES 391
#define FULLM 0xffffffffu

// ---------------- device scratch ----------------
__device__ float    d_Q[NN * 64];
__device__ float    d_K[NN * 64];
__device__ float    d_V[NN * 64];
__device__ float    d_hb[NN * 64];
__device__ unsigned d_sbufp[NE * 32];   // bf16x2-packed s, EDGE order
__device__ float    d_scoreb[NE * 8];   // EDGE order
__device__ __half2  d_eprh[NE * 32];    // fp16-packed epre (edge order)
__device__ float    d_t1[NN * 64];
__device__ float    d_t2[NN * 64];
__device__ int      d_rowoff[NN + 1];
__device__ int      d_counts[NN];
__device__ int      d_cursor[NN];
__device__ int      d_col[NE];
__device__ int      d_srcp[NE];
__device__ float    d_stats[384];

__device__ __forceinline__ unsigned cvt_tf32(float x) {
    unsigned r;
    asm("cvt.rna.tf32.f32 %0, %1;" : "=r"(r) : "f"(x));
    return r;
}

#define MMA_TF32(C, A0, A1, A2, A3, B0, B1)                                   \
    asm volatile(                                                             \
        "mma.sync.aligned.m16n8k8.row.col.f32.tf32.tf32.f32 "                 \
        "{%0,%1,%2,%3}, {%4,%5,%6,%7}, {%8,%9}, {%0,%1,%2,%3};"               \
        : "+f"(C[0]), "+f"(C[1]), "+f"(C[2]), "+f"(C[3])                      \
        : "r"(A0), "r"(A1), "r"(A2), "r"(A3), "r"(B0), "r"(B1))

// ---------------- zero ----------------
__global__ void k_zero() {
    int i = blockIdx.x * blockDim.x + threadIdx.x;
    if (i < NN) d_counts[i] = 0;
    if (i < 384) d_stats[i] = 0.f;
}

__global__ void k_scan() {
    __shared__ int sh[1024];
    int tid = threadIdx.x;
    const int per = (NN + 1023) / 1024;
    int s = tid * per;
    int e = s + per; if (e > NN) e = NN;
    int sum = 0;
    for (int i = s; i < e && i < NN; i++) sum += d_counts[i];
    sh[tid] = sum;
    __syncthreads();
    for (int off = 1; off < 1024; off <<= 1) {
        int t = (tid >= off) ? sh[tid - off] : 0;
        __syncthreads();
        sh[tid] += t;
        __syncthreads();
    }
    int run = sh[tid] - sum;
    for (int i = s; i < e && i < NN; i++) {
        d_rowoff[i] = run;
        d_cursor[i] = run;
        run += d_counts[i];
    }
    if (tid == 1023) d_rowoff[NN] = sh[1023];
}

__global__ void k_fill(const int* __restrict__ eidx) {
    int e = blockIdx.x * blockDim.x + threadIdx.x;
    if (e < NE) {
        int dst = eidx[NE + e];
        int p = atomicAdd(&d_cursor[dst], 1);
        d_col[p] = e;
        d_srcp[p] = eidx[e];
    }
}

// ---------------- Q,K,V via tf32 MMA (+ fused degree count) ----------------
__global__ void __launch_bounds__(256) k_qkv(const float* __restrict__ x,
                                             const float* __restrict__ Wq,
                                             const float* __restrict__ bq,
                                             const float* __restrict__ Wk,
                                             const float* __restrict__ Wv,
                                             const int* __restrict__ eidx) {
    extern __shared__ float sm[];
    float* sX  = sm;
    float* sWT = sm + 8704;
    int tid = threadIdx.x;

    for (int e = blockIdx.x * 256 + tid; e < NE; e += gridDim.x * 256)
        atomicAdd(&d_counts[eidx[NE + e]], 1);

    const int tileBase = blockIdx.x * 128;
    for (int i = tid; i < 8192; i += 256) {
        int r = i >> 6, c = i & 63;
        int n = tileBase + r;
        sX[r * 68 + c] = (n < NN) ? x[(size_t)n * 64 + c] : 0.f;
    }
    for (int i = tid; i < 4096; i += 256) {
        int k = i >> 6, n = i & 63;
        int t7 = k & 7;
        int kd = (k & ~7) + ((t7 & 3) << 1) + (t7 >> 2);
        sWT[n * 72 + kd]         = __uint_as_float(cvt_tf32(Wq[i]));
        sWT[(n + 64) * 72 + kd]  = __uint_as_float(cvt_tf32(Wk[i]));
        sWT[(n + 128) * 72 + kd] = __uint_as_float(cvt_tf32(Wv[i]));
    }
    __syncthreads();

    const int l = tid & 31, w16 = (tid >> 5) * 16, g = l >> 2, tig = l & 3;
    const int rA0 = (w16 + g) * 68, rA1 = rA0 + 8 * 68;

    float c[24][4];
#pragma unroll
    for (int nt = 0; nt < 24; nt++)
#pragma unroll
        for (int s = 0; s < 4; s++) c[nt][s] = 0.f;

#pragma unroll
    for (int ks = 0; ks < 8; ks++) {
        unsigned a0 = cvt_tf32(sX[rA0 + ks * 8 + tig]);
        unsigned a1 = cvt_tf32(sX[rA1 + ks * 8 + tig]);
        unsigned a2 = cvt_tf32(sX[rA0 + ks * 8 + tig + 4]);
        unsigned a3 = cvt_tf32(sX[rA1 + ks * 8 + tig + 4]);
#pragma unroll
        for (int nt = 0; nt < 24; nt++) {
            float2 bb = *(const float2*)&sWT[(nt * 8 + g) * 72 + ks * 8 + 2 * tig];
            MMA_TF32(c[nt], a0, a1, a2, a3, __float_as_uint(bb.x), __float_as_uint(bb.y));
        }
    }

    int n0 = tileBase + w16 + g, n1 = n0 + 8;
    bool v0r = n0 < NN, v1r = n1 < NN;
#pragma unroll
    for (int nt = 0; nt < 24; nt++) {
        int col = (nt & 7) * 8 + 2 * tig;
        float b0 = 0.f, b1 = 0.f;
        float* base;
        if (nt < 8)       { base = d_Q; b0 = __ldg(&bq[col]); b1 = __ldg(&bq[col + 1]); }
        else if (nt < 16) { base = d_K; }
        else              { base = d_V; }
        if (v0r) *(float2*)&base[(size_t)n0 * 64 + col] = make_float2(c[nt][0] + b0, c[nt][1] + b1);
        if (v1r) *(float2*)&base[(size_t)n1 * 64 + col] = make_float2(c[nt][2] + b0, c[nt][3] + b1);
    }
}

// ---------------- persistent edge kernel: m16 split-N, pair-ks B, 2 blk/SM ---
// smem floats: sWeT2[10240]@0, sWOeT2[5120]@10240, sStats[128]@15360,
//              sCst[256]@15488, sA[128x68=8704]@15744 -> 24448 fl = 97,792 B
__device__ __forceinline__ void prefetch_tile(float* dst, const float* src, int tid) {
#pragma unroll
    for (int i = tid; i < 2048; i += 256) {
        int r = i >> 4, c4 = (i & 15) << 2;
        unsigned daddr = (unsigned)__cvta_generic_to_shared(dst + r * 68 + c4);
        asm volatile("cp.async.cg.shared.global [%0], [%1], 16;"
                     :: "r"(daddr), "l"(src + r * 64 + c4));
    }
}

__global__ void __launch_bounds__(256, 2) k_edge_mma(const float* __restrict__ ea,
                                                     const int* __restrict__ eidx,
                                                     const float* __restrict__ We,
                                                     const float* __restrict__ be,
                                                     const float* __restrict__ Aw,
                                                     const float* __restrict__ WOe,
                                                     const float* __restrict__ bOe) {
    extern __shared__ float smem[];
    float* sWeT2  = smem;
    float* sWOeT2 = smem + 10240;
    float* sStats = smem + 15360;
    float* sCst   = smem + 15488;
    float* sA     = smem + 15744;

    const int tid = threadIdx.x;

    if (tid < 128) sStats[tid] = 0.f;
    // pair-ks B layout: slot ((nt*8+g)*4+tig)*20 + ks*2 + half stores W[ks*8+tig+4*half][nt*8+g]
    for (int i = tid; i < 8192; i += 256) {
        int k = i >> 7, n = i & 127;
        int nt = n >> 3, g2 = n & 7;
        int ks = k >> 3, t7 = k & 7;
        sWeT2[((nt * 8 + g2) * 4 + (t7 & 3)) * 20 + ks * 2 + (t7 >> 2)] =
            __uint_as_float(cvt_tf32(We[i]));
    }
    for (int i = tid; i < 4096; i += 256) {
        int k = i >> 6, n = i & 63;
        int nt = n >> 3, g2 = n & 7;
        int ks = k >> 3, t7 = k & 7;
        sWOeT2[((nt * 8 + g2) * 4 + (t7 & 3)) * 20 + ks * 2 + (t7 >> 2)] =
            __uint_as_float(cvt_tf32(WOe[i]));
    }
    // epilogue constant tables: per (h, tig)
    if (tid < 32) {
        int h = tid >> 2, tg = tid & 3;
        sCst[tid * 4 + 0] = __ldg(&be[h * 16 + 2 * tg]);
        sCst[tid * 4 + 1] = __ldg(&be[h * 16 + 2 * tg + 1]);
        sCst[tid * 4 + 2] = __ldg(&be[h * 16 + 8 + 2 * tg]);
        sCst[tid * 4 + 3] = __ldg(&be[h * 16 + 9 + 2 * tg]);
        sCst[128 + tid * 4 + 0] = __ldg(&Aw[(2 * tg) * 8 + h]);
        sCst[128 + tid * 4 + 1] = __ldg(&Aw[(2 * tg + 1) * 8 + h]);
        sCst[128 + tid * 4 + 2] = __ldg(&bOe[h * 8 + 2 * tg]);
        sCst[128 + tid * 4 + 3] = __ldg(&bOe[h * 8 + 2 * tg + 1]);
    }

    const int l = tid & 31;
    const int w16 = (tid >> 5) * 16;
    const int g = l >> 2, tig = l & 3;
    const int rA0 = (w16 + g) * 68;
    const int rA1 = rA0 + 8 * 68;

    int tile = blockIdx.x;
    if (tile < NTILES) {
        prefetch_tile(sA, ea + (size_t)tile * 8192, tid);
        asm volatile("cp.async.commit_group;");
    }

    for (; tile < NTILES; tile += gridDim.x) {
        asm volatile("cp.async.wait_group 0;");
        __syncthreads();
        const int tileBase = tile * 128;

        const int e0 = tileBase + w16 + g;
        const int e1 = e0 + 8;
        int src0 = __ldg(&eidx[e0]), dst0 = __ldg(&eidx[NE + e0]);
        int src1 = __ldg(&eidx[e1]), dst1 = __ldg(&eidx[NE + e1]);
        const float* K0 = d_K + (size_t)src0 * 64;
        const float* Q0 = d_Q + (size_t)dst0 * 64;
        const float* K1 = d_K + (size_t)src1 * 64;
        const float* Q1 = d_Q + (size_t)dst1 * 64;

        float c2[8][4];       // GEMM2 accumulators
        float sreg[4][4];     // half-0 s values

#pragma unroll
        for (int nh = 0; nh < 2; nh++) {
            // ---- GEMM1 half: N=64 ----
            float c1[8][4];
#pragma unroll
            for (int nt = 0; nt < 8; nt++)
#pragma unroll
                for (int s = 0; s < 4; s++) c1[nt][s] = 0.f;

#pragma unroll
            for (int p = 0; p < 4; p++) {
                int ka = 2 * p, kb = 2 * p + 1;
                unsigned a0 = cvt_tf32(sA[rA0 + ka * 8 + tig]);
                unsigned a1 = cvt_tf32(sA[rA1 + ka * 8 + tig]);
                unsigned a2 = cvt_tf32(sA[rA0 + ka * 8 + tig + 4]);
                unsigned a3 = cvt_tf32(sA[rA1 + ka * 8 + tig + 4]);
                unsigned a4 = cvt_tf32(sA[rA0 + kb * 8 + tig]);
                unsigned a5 = cvt_tf32(sA[rA1 + kb * 8 + tig]);
                unsigned a6 = cvt_tf32(sA[rA0 + kb * 8 + tig + 4]);
                unsigned a7 = cvt_tf32(sA[rA1 + kb * 8 + tig + 4]);
#pragma unroll
                for (int nt = 0; nt < 8; nt++) {
                    float4 bb = *(const float4*)
                        &sWeT2[(((nh * 8 + nt) * 8 + g) * 4 + tig) * 20 + p * 4];
                    MMA_TF32(c1[nt], a0, a1, a2, a3, __float_as_uint(bb.x), __float_as_uint(bb.y));
                    MMA_TF32(c1[nt], a4, a5, a6, a7, __float_as_uint(bb.z), __float_as_uint(bb.w));
                }
            }

            // ---- epilogue for heads nh*4 .. nh*4+3 ----
#pragma unroll
            for (int hh = 0; hh < 4; hh++) {
                const int h = nh * 4 + hh;
                const int nt = 2 * hh;
                const int dc = h * 8 + 2 * tig;
                float4 cw = *(const float4*)&sCst[(h * 4 + tig) * 4];        // bw0,bw1,bb0,bb1
                float4 cx = *(const float4*)&sCst[128 + (h * 4 + tig) * 4];  // aw0,aw1,bo0,bo1

                float2 ka = *(const float2*)(K0 + dc);
                float2 qa = *(const float2*)(Q0 + dc);
                float2 kb = *(const float2*)(K1 + dc);
                float2 qb = *(const float2*)(Q1 + dc);
                float2 eaA = *(const float2*)&sA[rA0 + dc];
                float2 eaB = *(const float2*)&sA[rA1 + dc];

                float t00 = (ka.x + qa.x) * (c1[nt][0] + cw.x);
                float t01 = (ka.y + qa.y) * (c1[nt][1] + cw.y);
                float t10 = (kb.x + qb.x) * (c1[nt][2] + cw.x);
                float t11 = (kb.y + qb.y) * (c1[nt][3] + cw.y);
                float s00 = fmaxf(copysignf(sqrtf(fabsf(t00)), t00) + (c1[nt + 1][0] + cw.z), 0.f);
                float s01 = fmaxf(copysignf(sqrtf(fabsf(t01)), t01) + (c1[nt + 1][1] + cw.w), 0.f);
                float s10 = fmaxf(copysignf(sqrtf(fabsf(t10)), t10) + (c1[nt + 1][2] + cw.z), 0.f);
                float s11 = fmaxf(copysignf(sqrtf(fabsf(t11)), t11) + (c1[nt + 1][3] + cw.w), 0.f);

                unsigned pk0, pk1;
                asm("cvt.rn.bf16x2.f32 %0, %1, %2;" : "=r"(pk0) : "f"(s01), "f"(s00));
                asm("cvt.rn.bf16x2.f32 %0, %1, %2;" : "=r"(pk1) : "f"(s11), "f"(s10));
                d_sbufp[(size_t)e0 * 32 + h * 4 + tig] = pk0;
                d_sbufp[(size_t)e1 * 32 + h * 4 + tig] = pk1;

                if (nh == 0) {
                    sreg[hh][0] = s00; sreg[hh][1] = s01;
                    sreg[hh][2] = s10; sreg[hh][3] = s11;
                } else {
                    *(float2*)&sA[rA0 + dc] = make_float2(s00, s01);
                    *(float2*)&sA[rA1 + dc] = make_float2(s10, s11);
                }

                float p0 = s00 * cx.x + s01 * cx.y;
                float p1 = s10 * cx.x + s11 * cx.y;
                p0 += __shfl_xor_sync(FULLM, p0, 1);
                p0 += __shfl_xor_sync(FULLM, p0, 2);
                p1 += __shfl_xor_sync(FULLM, p1, 1);
                p1 += __shfl_xor_sync(FULLM, p1, 2);
                if (tig == 0) {
                    d_scoreb[(size_t)e0 * 8 + h] = fminf(fmaxf(p0, -5.f), 5.f);
                    d_scoreb[(size_t)e1 * 8 + h] = fminf(fmaxf(p1, -5.f), 5.f);
                }

                c2[h][0] = eaA.x + cx.z; c2[h][1] = eaA.y + cx.w;
                c2[h][2] = eaB.x + cx.z; c2[h][3] = eaB.y + cx.w;
            }
        }

        // flush stashed half-0 s into sA (cols 0..31)
#pragma unroll
        for (int hh = 0; hh < 4; hh++) {
            const int dc = hh * 8 + 2 * tig;
            *(float2*)&sA[rA0 + dc] = make_float2(sreg[hh][0], sreg[hh][1]);
            *(float2*)&sA[rA1 + dc] = make_float2(sreg[hh][2], sreg[hh][3]);
        }
        __syncwarp();

        // ---- GEMM2: epre += s @ WOe ----
#pragma unroll
        for (int p = 0; p < 4; p++) {
            int ka = 2 * p, kb = 2 * p + 1;
            unsigned a0 = cvt_tf32(sA[rA0 + ka * 8 + tig]);
            unsigned a1 = cvt_tf32(sA[rA1 + ka * 8 + tig]);
            unsigned a2 = cvt_tf32(sA[rA0 + ka * 8 + tig + 4]);
            unsigned a3 = cvt_tf32(sA[rA1 + ka * 8 + tig + 4]);
            unsigned a4 = cvt_tf32(sA[rA0 + kb * 8 + tig]);
            unsigned a5 = cvt_tf32(sA[rA1 + kb * 8 + tig]);
            unsigned a6 = cvt_tf32(sA[rA0 + kb * 8 + tig + 4]);
            unsigned a7 = cvt_tf32(sA[rA1 + kb * 8 + tig + 4]);
#pragma unroll
            for (int h = 0; h < 8; h++) {
                float4 bb = *(const float4*)
                    &sWOeT2[((h * 8 + g) * 4 + tig) * 20 + p * 4];
                MMA_TF32(c2[h], a0, a1, a2, a3, __float_as_uint(bb.x), __float_as_uint(bb.y));
                MMA_TF32(c2[h], a4, a5, a6, a7, __float_as_uint(bb.z), __float_as_uint(bb.w));
            }
        }

        // ---- all warps done with sA: start next-tile prefetch ----
        __syncthreads();
        int next = tile + gridDim.x;
        if (next < NTILES) {
            prefetch_tile(sA, ea + (size_t)next * 8192, tid);
            asm volatile("cp.async.commit_group;");
        }

        // ---- epilogue 2: epre (fp16) + BN stats (overlaps prefetch) ----
#pragma unroll
        for (int h = 0; h < 8; h++) {
            int wi = h * 4 + tig;
            int col = h * 8 + 2 * tig;
            float* cA = c2[h];
            d_eprh[(size_t)e0 * 32 + wi] = __floats2half2_rn(cA[0], cA[1]);
            d_eprh[(size_t)e1 * 32 + wi] = __floats2half2_rn(cA[2], cA[3]);
            float s0 = cA[0] + cA[2];
            float s1 = cA[1] + cA[3];
            float q0 = cA[0] * cA[0] + cA[2] * cA[2];
            float q1 = cA[1] * cA[1] + cA[3] * cA[3];
#pragma unroll
            for (int off = 4; off < 32; off <<= 1) {
                s0 += __shfl_xor_sync(FULLM, s0, off);
                s1 += __shfl_xor_sync(FULLM, s1, off);
                q0 += __shfl_xor_sync(FULLM, q0, off);
                q1 += __shfl_xor_sync(FULLM, q1, off);
            }
            if (l < 4) {
                atomicAdd(&sStats[col], s0);
                atomicAdd(&sStats[col + 1], s1);
                atomicAdd(&sStats[64 + col], q0);
                atomicAdd(&sStats[64 + col + 1], q1);
            }
        }
    }

    __syncthreads();
    if (tid < 64) {
        atomicAdd(&d_stats[tid], sStats[tid]);
        atomicAdd(&d_stats[64 + tid], sStats[64 + tid]);
    }
}

// ---------------- node gather + eout slice ----------------
__global__ void __launch_bounds__(256) k_node(const float* __restrict__ VeRow,
                                              const float* __restrict__ dcoef,
                                              const float* __restrict__ g1e,
                                              const float* __restrict__ b1e,
                                              float* __restrict__ eout) {
    __shared__ float seSc[64], seSh[64];
    int tid = threadIdx.x;
    if (tid < 64) {
        float mu = d_stats[tid] / NE;
        float var = d_stats[64 + tid] / NE - mu * mu;
        float sc = g1e[tid] * rsqrtf(var + 1e-5f);
        seSc[tid] = sc;
        seSh[tid] = b1e[tid] - mu * sc;
    }
    __syncthreads();

    int l = tid & 31;
    int n = blockIdx.x * 8 + (tid >> 5);
    if (n < NN) {
        int start = d_rowoff[n], end = d_rowoff[n + 1];
        int h0 = l >> 3;
        int wsel = l >> 1;
        float accV0 = 0.f, accV1 = 0.f, accR0 = 0.f, accR1 = 0.f, den0 = 0.f, den1 = 0.f;
        for (int j = start; j < end; j += 32) {
            int m = end - j; if (m > 32) m = 32;
            int e_l = 0, s_l = 0;
            if (l < m) {
                e_l = __ldg(&d_col[j + l]);
                s_l = __ldg(&d_srcp[j + l]);
            }
#pragma unroll 4
            for (int t = 0; t < m; t++) {
                int e = __shfl_sync(FULLM, e_l, t);
                int src = __shfl_sync(FULLM, s_l, t);
                float ex0 = __expf(__ldg(&d_scoreb[(size_t)e * 8 + h0]));
                float ex1 = __expf(__ldg(&d_scoreb[(size_t)e * 8 + h0 + 4]));
                den0 += ex0; den1 += ex1;
                accV0 += __ldg(&d_V[(size_t)src * 64 + l]) * ex0;
                accV1 += __ldg(&d_V[(size_t)src * 64 + 32 + l]) * ex1;
                unsigned wlo = __ldg(&d_sbufp[(size_t)e * 32 + wsel]);
                unsigned whi = __ldg(&d_sbufp[(size_t)e * 32 + 16 + wsel]);
                float sb0 = __uint_as_float((l & 1) ? (wlo & 0xffff0000u) : (wlo << 16));
                float sb1 = __uint_as_float((l & 1) ? (whi & 0xffff0000u) : (whi << 16));
                accR0 += sb0 * ex0;
                accR1 += sb1 * ex1;
            }
        }
        float inv0 = 1.f / (den0 + 1e-16f), inv1 = 1.f / (den1 + 1e-16f);
        float rv0 = accR0 * inv0, rv1 = accR1 * inv1;
        float out0 = accV0 * inv0, out1 = accV1 * inv1;

        int gbase = l & 24;
#pragma unroll
        for (int k = 0; k < 8; k++) {
            float r0 = __shfl_sync(FULLM, rv0, gbase + k);
            float r1 = __shfl_sync(FULLM, rv1, gbase + k);
            out0 += r0 * VeRow[k * 64 + l];
            out1 += r1 * VeRow[k * 64 + l + 32];
        }
        float deg = (float)(end - start);
        float ld = logf(deg + 1.f);
        out0 *= (dcoef[l * 2] + ld * dcoef[l * 2 + 1]);
        out1 *= (dcoef[(l + 32) * 2] + ld * dcoef[(l + 32) * 2 + 1]);
        d_hb[(size_t)n * 64 + l] = out0;
        d_hb[(size_t)n * 64 + 32 + l] = out1;
    }

    // ---- eout slice: 1024 uint4 per block ----
    {
        const __half2* eph = d_eprh;
        int base4 = blockIdx.x * 1024;
        for (int i = tid; i < 1024; i += 256) {
            int idx = base4 + i;
            int j0 = idx * 4;
            int cbase = (j0 & 31) * 2;
            float4 raw = __ldg((const float4*)(eph + j0));
            const __half2* hp = (const __half2*)&raw;
            float4 o0, o1;
            float2 v0 = __half22float2(hp[0]);
            float2 v1 = __half22float2(hp[1]);
            o0.x = v0.x * seSc[cbase + 0] + seSh[cbase + 0];
            o0.y = v0.y * seSc[cbase + 1] + seSh[cbase + 1];
            o0.z = v1.x * seSc[cbase + 2] + seSh[cbase + 2];
            o0.w = v1.y * seSc[cbase + 3] + seSh[cbase + 3];
            float2 v2 = __half22float2(hp[2]);
            float2 v3 = __half22float2(hp[3]);
            o1.x = v2.x * seSc[cbase + 4] + seSh[cbase + 4];
            o1.y = v2.y * seSc[cbase + 5] + seSh[cbase + 5];
            o1.z = v3.x * seSc[cbase + 6] + seSh[cbase + 6];
            o1.w = v3.y * seSc[cbase + 7] + seSh[cbase + 7];
            float4* op = (float4*)(eout + (size_t)j0 * 2);
            op[0] = o0;
            op[1] = o1;
        }
    }
}

// ---------------- t1 = x + hb @ WOh + bOh via MMA + BN1h stats ----------------
__global__ void __launch_bounds__(256) k_t1(const float* __restrict__ x,
                                            const float* __restrict__ WOh,
                                            const float* __restrict__ bOh) {
    extern __shared__ float sm[];
    float* sA = sm;
    float* sWT = sm + 8704;
    float* sStats = sm + 13312;
    int tid = threadIdx.x;
    if (tid < 128) sStats[tid] = 0.f;
    const int tileBase = blockIdx.x * 128;
    for (int i = tid; i < 8192; i += 256) {
        int r = i >> 6, c = i & 63;
        int n = tileBase + r;
        sA[r * 68 + c] = (n < NN) ? d_hb[(size_t)n * 64 + c] : 0.f;
    }
    for (int i = tid; i < 4096; i += 256) {
        int k = i >> 6, n = i & 63;
        int t7 = k & 7;
        int kd = (k & ~7) + ((t7 & 3) << 1) + (t7 >> 2);
        sWT[n * 72 + kd] = __uint_as_float(cvt_tf32(WOh[i]));
    }
    __syncthreads();

    const int l = tid & 31, w16 = (tid >> 5) * 16, g = l >> 2, tig = l & 3;
    const int rA0 = (w16 + g) * 68, rA1 = rA0 + 8 * 68;
    int n0 = tileBase + w16 + g, n1 = n0 + 8;
    bool v0r = n0 < NN, v1r = n1 < NN;

    float c[8][4];
#pragma unroll
    for (int nt = 0; nt < 8; nt++) {
        int col = nt * 8 + 2 * tig;
        float b0 = __ldg(&bOh[col]), b1 = __ldg(&bOh[col + 1]);
        float2 x0v = v0r ? *(const float2*)&x[(size_t)n0 * 64 + col] : make_float2(0.f, 0.f);
        float2 x1v = v1r ? *(const float2*)&x[(size_t)n1 * 64 + col] : make_float2(0.f, 0.f);
        c[nt][0] = b0 + x0v.x; c[nt][1] = b1 + x0v.y;
        c[nt][2] = b0 + x1v.x; c[nt][3] = b1 + x1v.y;
    }

#pragma unroll
    for (int ks = 0; ks < 8; ks++) {
        unsigned a0 = cvt_tf32(sA[rA0 + ks * 8 + tig]);
        unsigned a1 = cvt_tf32(sA[rA1 + ks * 8 + tig]);
        unsigned a2 = cvt_tf32(sA[rA0 + ks * 8 + tig + 4]);
        unsigned a3 = cvt_tf32(sA[rA1 + ks * 8 + tig + 4]);
#pragma unroll
        for (int nt = 0; nt < 8; nt++) {
            float2 bb = *(const float2*)&sWT[(nt * 8 + g) * 72 + ks * 8 + 2 * tig];
            MMA_TF32(c[nt], a0, a1, a2, a3, __float_as_uint(bb.x), __float_as_uint(bb.y));
        }
    }

#pragma unroll
    for (int nt = 0; nt < 8; nt++) {
        int col = nt * 8 + 2 * tig;
        if (v0r) *(float2*)&d_t1[(size_t)n0 * 64 + col] = make_float2(c[nt][0], c[nt][1]);
        if (v1r) *(float2*)&d_t1[(size_t)n1 * 64 + col] = make_float2(c[nt][2], c[nt][3]);
        float a0 = v0r ? c[nt][0] : 0.f, a1 = v0r ? c[nt][1] : 0.f;
        float a2 = v1r ? c[nt][2] : 0.f, a3 = v1r ? c[nt][3] : 0.f;
        float s0 = a0 + a2, s1 = a1 + a3;
        float q0 = a0 * a0 + a2 * a2, q1 = a1 * a1 + a3 * a3;
#pragma unroll
        for (int off = 4; off < 32; off <<= 1) {
            s0 += __shfl_xor_sync(FULLM, s0, off);
            s1 += __shfl_xor_sync(FULLM, s1, off);
            q0 += __shfl_xor_sync(FULLM, q0, off);
            q1 += __shfl_xor_sync(FULLM, q1, off);
        }
        if (l < 4) {
            atomicAdd(&sStats[col], s0);
            atomicAdd(&sStats[col + 1], s1);
            atomicAdd(&sStats[64 + col], q0);
            atomicAdd(&sStats[64 + col + 1], q1);
        }
    }
    __syncthreads();
    if (tid < 64) {
        atomicAdd(&d_stats[128 + tid], sStats[tid]);
        atomicAdd(&d_stats[192 + tid], sStats[64 + tid]);
    }
}

// ---------------- MLP via MMA ----------------
__global__ void __launch_bounds__(256) k_mlp(const float* __restrict__ g1h,
                                             const float* __restrict__ be1h,
                                             const float* __restrict__ W1,
                                             const float* __restrict__ b1v,
                                             const float* __restrict__ W2,
                                             const float* __restrict__ b2v) {
    extern __shared__ float sm[];
    float* sW2T = sm;
    float* sA   = sm + 8704;
    float* sW1T = sm + 17408;
    float* sMid = sm + 8704;
    float* sBNc = sm + 26624;
    float* sBNs = sm + 26688;
    float* sStats = sm + 26752;
    int tid = threadIdx.x;
    if (tid < 128) sStats[tid] = 0.f;
    if (tid < 64) {
        float mu = d_stats[128 + tid] / NN;
        float var = d_stats[192 + tid] / NN - mu * mu;
        float sc = g1h[tid] * rsqrtf(var + 1e-5f);
        sBNc[tid] = sc;
        sBNs[tid] = be1h[tid] - mu * sc;
    }
    for (int i = tid; i < 8192; i += 256) {
        int k = i >> 6, n = i & 63;
        int t7 = k & 7;
        int kd = (k & ~7) + ((t7 & 3) << 1) + (t7 >> 2);
        sW2T[n * 136 + kd] = __uint_as_float(cvt_tf32(W2[i]));
    }
    for (int i = tid; i < 8192; i += 256) {
        int k = i >> 7, n = i & 127;
        int t7 = k & 7;
        int kd = (k & ~7) + ((t7 & 3) << 1) + (t7 >> 2);
        sW1T[n * 72 + kd] = __uint_as_float(cvt_tf32(W1[i]));
    }
    __syncthreads();

    const int tileBase = blockIdx.x * 128;
    for (int i = tid; i < 8192; i += 256) {
        int r = i >> 6, c = i & 63;
        int n = tileBase + r;
        sA[r * 68 + c] = (n < NN) ? d_t1[(size_t)n * 64 + c] * sBNc[c] + sBNs[c] : 0.f;
    }
    __syncthreads();

    const int l = tid & 31, w16 = (tid >> 5) * 16, g = l >> 2, tig = l & 3;
    const int rA0 = (w16 + g) * 68, rA1 = rA0 + 8 * 68;

    float c1[16][4];
#pragma unroll
    for (int nt = 0; nt < 16; nt++) {
        int col = nt * 8 + 2 * tig;
        float b0 = __ldg(&b1v[col]), b1 = __ldg(&b1v[col + 1]);
        c1[nt][0] = b0; c1[nt][1] = b1; c1[nt][2] = b0; c1[nt][3] = b1;
    }
#pragma unroll
    for (int ks = 0; ks < 8; ks++) {
        unsigned a0 = cvt_tf32(sA[rA0 + ks * 8 + tig]);
        unsigned a1 = cvt_tf32(sA[rA1 + ks * 8 + tig]);
        unsigned a2 = cvt_tf32(sA[rA0 + ks * 8 + tig + 4]);
        unsigned a3 = cvt_tf32(sA[rA1 + ks * 8 + tig + 4]);
#pragma unroll
        for (int nt = 0; nt < 16; nt++) {
            float2 bb = *(const float2*)&sW1T[(nt * 8 + g) * 72 + ks * 8 + 2 * tig];
            MMA_TF32(c1[nt], a0, a1, a2, a3, __float_as_uint(bb.x), __float_as_uint(bb.y));
        }
    }

    float h1r[8][4];
#pragma unroll
    for (int nt = 0; nt < 8; nt++) {
        int col = nt * 8 + 2 * tig;
        float2 r0 = *(const float2*)&sA[rA0 + col];
        float2 r1 = *(const float2*)&sA[rA1 + col];
        h1r[nt][0] = r0.x; h1r[nt][1] = r0.y;
        h1r[nt][2] = r1.x; h1r[nt][3] = r1.y;
    }
    __syncthreads();

    const int rM0 = (w16 + g) * 132, rM1 = rM0 + 8 * 132;
#pragma unroll
    for (int nt = 0; nt < 16; nt++) {
        int col = nt * 8 + 2 * tig;
        *(float2*)&sMid[rM0 + col] = make_float2(fmaxf(c1[nt][0], 0.f), fmaxf(c1[nt][1], 0.f));
        *(float2*)&sMid[rM1 + col] = make_float2(fmaxf(c1[nt][2], 0.f), fmaxf(c1[nt][3], 0.f));
    }
    __syncthreads();

    float c2[8][4];
#pragma unroll
    for (int nt = 0; nt < 8; nt++) {
        int col = nt * 8 + 2 * tig;
        float b0 = __ldg(&b2v[col]), b1 = __ldg(&b2v[col + 1]);
        c2[nt][0] = h1r[nt][0] + b0; c2[nt][1] = h1r[nt][1] + b1;
        c2[nt][2] = h1r[nt][2] + b0; c2[nt][3] = h1r[nt][3] + b1;
    }
#pragma unroll
    for (int ks = 0; ks < 16; ks++) {
        unsigned a0 = cvt_tf32(sMid[rM0 + ks * 8 + tig]);
        unsigned a1 = cvt_tf32(sMid[rM1 + ks * 8 + tig]);
        unsigned a2 = cvt_tf32(sMid[rM0 + ks * 8 + tig + 4]);
        unsigned a3 = cvt_tf32(sMid[rM1 + ks * 8 + tig + 4]);
#pragma unroll
        for (int nt = 0; nt < 8; nt++) {
            float2 bb = *(const float2*)&sW2T[(nt * 8 + g) * 136 + ks * 8 + 2 * tig];
            MMA_TF32(c2[nt], a0, a1, a2, a3, __float_as_uint(bb.x), __float_as_uint(bb.y));
        }
    }

    int n0 = tileBase + w16 + g, n1 = n0 + 8;
    bool v0r = n0 < NN, v1r = n1 < NN;
#pragma unroll
    for (int nt = 0; nt < 8; nt++) {
        int col = nt * 8 + 2 * tig;
        if (v0r) *(float2*)&d_t2[(size_t)n0 * 64 + col] = make_float2(c2[nt][0], c2[nt][1]);
        if (v1r) *(float2*)&d_t2[(size_t)n1 * 64 + col] = make_float2(c2[nt][2], c2[nt][3]);
        float a0 = v0r ? c2[nt][0] : 0.f, a1 = v0r ? c2[nt][1] : 0.f;
        float a2 = v1r ? c2[nt][2] : 0.f, a3 = v1r ? c2[nt][3] : 0.f;
        float s0 = a0 + a2, s1 = a1 + a3;
        float q0 = a0 * a0 + a2 * a2, q1 = a1 * a1 + a3 * a3;
#pragma unroll
        for (int off = 4; off < 32; off <<= 1) {
            s0 += __shfl_xor_sync(FULLM, s0, off);
            s1 += __shfl_xor_sync(FULLM, s1, off);
            q0 += __shfl_xor_sync(FULLM, q0, off);
            q1 += __shfl_xor_sync(FULLM, q1, off);
        }
        if (l < 4) {
            atomicAdd(&sStats[col], s0);
            atomicAdd(&sStats[col + 1], s1);
            atomicAdd(&sStats[64 + col], q0);
            atomicAdd(&sStats[64 + col + 1], q1);
        }
    }
    __syncthreads();
    if (tid < 64) {
        atomicAdd(&d_stats[256 + tid], sStats[tid]);
        atomicAdd(&d_stats[320 + tid], sStats[64 + tid]);
    }
}

// ---------------- final h output ----------------
__global__ void k_hout(const float* __restrict__ g2h,
                       const float* __restrict__ b2h, float* __restrict__ out) {
    int idx0 = blockIdx.x * blockDim.x + threadIdx.x;
    int stride = gridDim.x * blockDim.x;
    int col = idx0 & 63;
    float mu = d_stats[256 + col] / NN;
    float var = d_stats[320 + col] / NN - mu * mu;
    float sc = g2h[col] * rsqrtf(var + 1e-5f);
    float sh = b2h[col] - mu * sc;
    for (int i = idx0; i < NN * 64; i += stride) out[i] = d_t2[i] * sc + sh;
}

// ---------------- launch ----------------
extern "C" void kernel_launch(void* const* d_in, const int* in_sizes, int n_in,
                              void* d_out, int out_size) {
    const float* x     = (const float*)d_in[0];
    const float* ea    = (const float*)d_in[1];
    const int*   eidx  = (const int*)d_in[2];
    const float* Wq    = (const float*)d_in[3];
    const float* bq    = (const float*)d_in[4];
    const float* Wk    = (const float*)d_in[5];
    const float* We    = (const float*)d_in[6];
    const float* be    = (const float*)d_in[7];
    const float* Wv    = (const float*)d_in[8];
    const float* Aw    = (const float*)d_in[9];
    const float* VeRow = (const float*)d_in[10];
    const float* dcoef = (const float*)d_in[11];
    const float* WOh   = (const float*)d_in[12];
    const float* bOh   = (const float*)d_in[13];
    const float* WOe   = (const float*)d_in[14];
    const float* bOe   = (const float*)d_in[15];
    const float* g1h   = (const float*)d_in[16];
    const float* b1h   = (const float*)d_in[17];
    const float* g1e   = (const float*)d_in[18];
    const float* b1e   = (const float*)d_in[19];
    const float* W1    = (const float*)d_in[20];
    const float* b1v   = (const float*)d_in[21];
    const float* W2    = (const float*)d_in[22];
    const float* b2v   = (const float*)d_in[23];
    const float* g2h   = (const float*)d_in[24];
    const float* b2h   = (const float*)d_in[25];
    float* out = (float*)d_out;

    const int edge_smem = 24448 * 4;   // 97,792 B -> 2 blocks/SM
    const int qkv_smem  = 22528 * 4;
    const int t1_smem   = 13440 * 4;
    const int mlp_smem  = 26880 * 4;
    cudaFuncSetAttribute(k_edge_mma, cudaFuncAttributeMaxDynamicSharedMemorySize, edge_smem);
    cudaFuncSetAttribute(k_qkv, cudaFuncAttributeMaxDynamicSharedMemorySize, qkv_smem);
    cudaFuncSetAttribute(k_t1, cudaFuncAttributeMaxDynamicSharedMemorySize, t1_smem);
    cudaFuncSetAttribute(k_mlp, cudaFuncAttributeMaxDynamicSharedMemorySize, mlp_smem);

    // k_edge_mma stays the 4th launch -> lands in the ncu capture slot.
    k_zero<<<196, 256>>>();
    k_qkv<<<NODE_TILES, 256, qkv_smem>>>(x, Wq, bq, Wk, Wv, eidx);
    k_scan<<<1, 1024>>>();
    k_edge_mma<<<296, 256, edge_smem>>>(ea, eidx, We, be, Aw, WOe, bOe);
    k_fill<<<3125, 256>>>(eidx);
    k_node<<<6250, 256>>>(VeRow, dcoef, g1e, b1e, out + (size_t)NN * 64);
    k_t1<<<NODE_TILES, 256, t1_smem>>>(x, WOh, bOh);
    k_mlp<<<NODE_TILES, 256, mlp_smem>>>(g1h, b1h, W1, b1v, W2, b2v);
    k_hout<<<512, 256>>>(g2h, b2h, out);
}

// round 16
// speedup vs baseline: 1.0615x; 1.0615x over previous
#include <cuda_runtime.h>
#include <cuda_fp16.h>
#include <math.h>

#define NN 50000
#define NE 800000
#define NTILES 6250
#define NODE_TILES 391
#define FULLM 0xffffffffu

// ---------------- device scratch ----------------
__device__ float    d_Q[NN * 64];
__device__ float    d_K[NN * 64];
__device__ unsigned d_Vh[NN * 32];      // fp16x2-packed V (cols 2i,2i+1)
__device__ float    d_hb[NN * 64];
__device__ unsigned d_sbufp[NE * 32];   // bf16x2-packed s, EDGE order
__device__ float    d_scoreb[NE * 8];   // EDGE order; stores exp(clamp(score))
__device__ __half2  d_eprh[NE * 32];    // fp16-packed epre (edge order)
__device__ float    d_t1[NN * 64];
__device__ float    d_t2[NN * 64];
__device__ int      d_rowoff[NN + 1];
__device__ int      d_counts[NN];
__device__ int      d_cursor[NN];
__device__ int      d_col[NE];
__device__ int      d_srcp[NE];
__device__ float    d_stats[384];

__device__ __forceinline__ unsigned cvt_tf32(float x) {
    unsigned r;
    asm("cvt.rna.tf32.f32 %0, %1;" : "=r"(r) : "f"(x));
    return r;
}

#define MMA_TF32(C, A0, A1, A2, A3, B0, B1)                                   \
    asm volatile(                                                             \
        "mma.sync.aligned.m16n8k8.row.col.f32.tf32.tf32.f32 "                 \
        "{%0,%1,%2,%3}, {%4,%5,%6,%7}, {%8,%9}, {%0,%1,%2,%3};"               \
        : "+f"(C[0]), "+f"(C[1]), "+f"(C[2]), "+f"(C[3])                      \
        : "r"(A0), "r"(A1), "r"(A2), "r"(A3), "r"(B0), "r"(B1))

// ---------------- zero ----------------
__global__ void k_zero() {
    int i = blockIdx.x * blockDim.x + threadIdx.x;
    if (i < NN) d_counts[i] = 0;
    if (i < 384) d_stats[i] = 0.f;
}

__global__ void k_scan() {
    __shared__ int sh[1024];
    int tid = threadIdx.x;
    const int per = (NN + 1023) / 1024;
    int s = tid * per;
    int e = s + per; if (e > NN) e = NN;
    int sum = 0;
    for (int i = s; i < e && i < NN; i++) sum += d_counts[i];
    sh[tid] = sum;
    __syncthreads();
    for (int off = 1; off < 1024; off <<= 1) {
        int t = (tid >= off) ? sh[tid - off] : 0;
        __syncthreads();
        sh[tid] += t;
        __syncthreads();
    }
    int run = sh[tid] - sum;
    for (int i = s; i < e && i < NN; i++) {
        d_rowoff[i] = run;
        d_cursor[i] = run;
        run += d_counts[i];
    }
    if (tid == 1023) d_rowoff[NN] = sh[1023];
}

__global__ void k_fill(const int* __restrict__ eidx) {
    int e = blockIdx.x * blockDim.x + threadIdx.x;
    if (e < NE) {
        int dst = eidx[NE + e];
        int p = atomicAdd(&d_cursor[dst], 1);
        d_col[p] = e;
        d_srcp[p] = eidx[e];
    }
}

// ---------------- Q,K,V via tf32 MMA (+ fused degree count) ----------------
__global__ void __launch_bounds__(256) k_qkv(const float* __restrict__ x,
                                             const float* __restrict__ Wq,
                                             const float* __restrict__ bq,
                                             const float* __restrict__ Wk,
                                             const float* __restrict__ Wv,
                                             const int* __restrict__ eidx) {
    extern __shared__ float sm[];
    float* sX  = sm;
    float* sWT = sm + 8704;
    int tid = threadIdx.x;

    for (int e = blockIdx.x * 256 + tid; e < NE; e += gridDim.x * 256)
        atomicAdd(&d_counts[eidx[NE + e]], 1);

    const int tileBase = blockIdx.x * 128;
    for (int i = tid; i < 8192; i += 256) {
        int r = i >> 6, c = i & 63;
        int n = tileBase + r;
        sX[r * 68 + c] = (n < NN) ? x[(size_t)n * 64 + c] : 0.f;
    }
    for (int i = tid; i < 4096; i += 256) {
        int k = i >> 6, n = i & 63;
        int t7 = k & 7;
        int kd = (k & ~7) + ((t7 & 3) << 1) + (t7 >> 2);
        sWT[n * 72 + kd]         = __uint_as_float(cvt_tf32(Wq[i]));
        sWT[(n + 64) * 72 + kd]  = __uint_as_float(cvt_tf32(Wk[i]));
        sWT[(n + 128) * 72 + kd] = __uint_as_float(cvt_tf32(Wv[i]));
    }
    __syncthreads();

    const int l = tid & 31, w16 = (tid >> 5) * 16, g = l >> 2, tig = l & 3;
    const int rA0 = (w16 + g) * 68, rA1 = rA0 + 8 * 68;

    float c[24][4];
#pragma unroll
    for (int nt = 0; nt < 24; nt++)
#pragma unroll
        for (int s = 0; s < 4; s++) c[nt][s] = 0.f;

#pragma unroll
    for (int ks = 0; ks < 8; ks++) {
        unsigned a0 = cvt_tf32(sX[rA0 + ks * 8 + tig]);
        unsigned a1 = cvt_tf32(sX[rA1 + ks * 8 + tig]);
        unsigned a2 = cvt_tf32(sX[rA0 + ks * 8 + tig + 4]);
        unsigned a3 = cvt_tf32(sX[rA1 + ks * 8 + tig + 4]);
#pragma unroll
        for (int nt = 0; nt < 24; nt++) {
            float2 bb = *(const float2*)&sWT[(nt * 8 + g) * 72 + ks * 8 + 2 * tig];
            MMA_TF32(c[nt], a0, a1, a2, a3, __float_as_uint(bb.x), __float_as_uint(bb.y));
        }
    }

    int n0 = tileBase + w16 + g, n1 = n0 + 8;
    bool v0r = n0 < NN, v1r = n1 < NN;
#pragma unroll
    for (int nt = 0; nt < 24; nt++) {
        int col = (nt & 7) * 8 + 2 * tig;
        if (nt < 8) {
            float b0 = __ldg(&bq[col]), b1 = __ldg(&bq[col + 1]);
            if (v0r) *(float2*)&d_Q[(size_t)n0 * 64 + col] = make_float2(c[nt][0] + b0, c[nt][1] + b1);
            if (v1r) *(float2*)&d_Q[(size_t)n1 * 64 + col] = make_float2(c[nt][2] + b0, c[nt][3] + b1);
        } else if (nt < 16) {
            if (v0r) *(float2*)&d_K[(size_t)n0 * 64 + col] = make_float2(c[nt][0], c[nt][1]);
            if (v1r) *(float2*)&d_K[(size_t)n1 * 64 + col] = make_float2(c[nt][2], c[nt][3]);
        } else {
            __half2 h0 = __floats2half2_rn(c[nt][0], c[nt][1]);
            __half2 h1 = __floats2half2_rn(c[nt][2], c[nt][3]);
            if (v0r) d_Vh[(size_t)n0 * 32 + (col >> 1)] = *(unsigned*)&h0;
            if (v1r) d_Vh[(size_t)n1 * 32 + (col >> 1)] = *(unsigned*)&h1;
        }
    }
}

// ---------------- persistent edge kernel: m16 split-N, pair-ks B, 2 blk/SM ---
__device__ __forceinline__ void prefetch_tile(float* dst, const float* src, int tid) {
#pragma unroll
    for (int i = tid; i < 2048; i += 256) {
        int r = i >> 4, c4 = (i & 15) << 2;
        unsigned daddr = (unsigned)__cvta_generic_to_shared(dst + r * 68 + c4);
        asm volatile("cp.async.cg.shared.global [%0], [%1], 16;"
                     :: "r"(daddr), "l"(src + r * 64 + c4));
    }
}

__global__ void __launch_bounds__(256, 2) k_edge_mma(const float* __restrict__ ea,
                                                     const int* __restrict__ eidx,
                                                     const float* __restrict__ We,
                                                     const float* __restrict__ be,
                                                     const float* __restrict__ Aw,
                                                     const float* __restrict__ WOe,
                                                     const float* __restrict__ bOe) {
    extern __shared__ float smem[];
    float* sWeT2  = smem;
    float* sWOeT2 = smem + 10240;
    float* sStats = smem + 15360;
    float* sCst   = smem + 15488;
    float* sA     = smem + 15744;

    const int tid = threadIdx.x;

    if (tid < 128) sStats[tid] = 0.f;
    for (int i = tid; i < 8192; i += 256) {
        int k = i >> 7, n = i & 127;
        int nt = n >> 3, g2 = n & 7;
        int ks = k >> 3, t7 = k & 7;
        sWeT2[((nt * 8 + g2) * 4 + (t7 & 3)) * 20 + ks * 2 + (t7 >> 2)] =
            __uint_as_float(cvt_tf32(We[i]));
    }
    for (int i = tid; i < 4096; i += 256) {
        int k = i >> 6, n = i & 63;
        int nt = n >> 3, g2 = n & 7;
        int ks = k >> 3, t7 = k & 7;
        sWOeT2[((nt * 8 + g2) * 4 + (t7 & 3)) * 20 + ks * 2 + (t7 >> 2)] =
            __uint_as_float(cvt_tf32(WOe[i]));
    }
    if (tid < 32) {
        int h = tid >> 2, tg = tid & 3;
        sCst[tid * 4 + 0] = __ldg(&be[h * 16 + 2 * tg]);
        sCst[tid * 4 + 1] = __ldg(&be[h * 16 + 2 * tg + 1]);
        sCst[tid * 4 + 2] = __ldg(&be[h * 16 + 8 + 2 * tg]);
        sCst[tid * 4 + 3] = __ldg(&be[h * 16 + 9 + 2 * tg]);
        sCst[128 + tid * 4 + 0] = __ldg(&Aw[(2 * tg) * 8 + h]);
        sCst[128 + tid * 4 + 1] = __ldg(&Aw[(2 * tg + 1) * 8 + h]);
        sCst[128 + tid * 4 + 2] = __ldg(&bOe[h * 8 + 2 * tg]);
        sCst[128 + tid * 4 + 3] = __ldg(&bOe[h * 8 + 2 * tg + 1]);
    }

    const int l = tid & 31;
    const int w16 = (tid >> 5) * 16;
    const int g = l >> 2, tig = l & 3;
    const int rA0 = (w16 + g) * 68;
    const int rA1 = rA0 + 8 * 68;

    int tile = blockIdx.x;
    if (tile < NTILES) {
        prefetch_tile(sA, ea + (size_t)tile * 8192, tid);
        asm volatile("cp.async.commit_group;");
    }

    for (; tile < NTILES; tile += gridDim.x) {
        asm volatile("cp.async.wait_group 0;");
        __syncthreads();
        const int tileBase = tile * 128;

        const int e0 = tileBase + w16 + g;
        const int e1 = e0 + 8;
        int src0 = __ldg(&eidx[e0]), dst0 = __ldg(&eidx[NE + e0]);
        int src1 = __ldg(&eidx[e1]), dst1 = __ldg(&eidx[NE + e1]);
        const float* K0 = d_K + (size_t)src0 * 64;
        const float* Q0 = d_Q + (size_t)dst0 * 64;
        const float* K1 = d_K + (size_t)src1 * 64;
        const float* Q1 = d_Q + (size_t)dst1 * 64;

        float c2[8][4];
        float sreg[4][4];

#pragma unroll
        for (int nh = 0; nh < 2; nh++) {
            float c1[8][4];
#pragma unroll
            for (int nt = 0; nt < 8; nt++)
#pragma unroll
                for (int s = 0; s < 4; s++) c1[nt][s] = 0.f;

#pragma unroll
            for (int p = 0; p < 4; p++) {
                int ka = 2 * p, kb = 2 * p + 1;
                unsigned a0 = cvt_tf32(sA[rA0 + ka * 8 + tig]);
                unsigned a1 = cvt_tf32(sA[rA1 + ka * 8 + tig]);
                unsigned a2 = cvt_tf32(sA[rA0 + ka * 8 + tig + 4]);
                unsigned a3 = cvt_tf32(sA[rA1 + ka * 8 + tig + 4]);
                unsigned a4 = cvt_tf32(sA[rA0 + kb * 8 + tig]);
                unsigned a5 = cvt_tf32(sA[rA1 + kb * 8 + tig]);
                unsigned a6 = cvt_tf32(sA[rA0 + kb * 8 + tig + 4]);
                unsigned a7 = cvt_tf32(sA[rA1 + kb * 8 + tig + 4]);
#pragma unroll
                for (int nt = 0; nt < 8; nt++) {
                    float4 bb = *(const float4*)
                        &sWeT2[(((nh * 8 + nt) * 8 + g) * 4 + tig) * 20 + p * 4];
                    MMA_TF32(c1[nt], a0, a1, a2, a3, __float_as_uint(bb.x), __float_as_uint(bb.y));
                    MMA_TF32(c1[nt], a4, a5, a6, a7, __float_as_uint(bb.z), __float_as_uint(bb.w));
                }
            }

#pragma unroll
            for (int hh = 0; hh < 4; hh++) {
                const int h = nh * 4 + hh;
                const int nt = 2 * hh;
                const int dc = h * 8 + 2 * tig;
                float4 cw = *(const float4*)&sCst[(h * 4 + tig) * 4];
                float4 cx = *(const float4*)&sCst[128 + (h * 4 + tig) * 4];

                float2 ka = *(const float2*)(K0 + dc);
                float2 qa = *(const float2*)(Q0 + dc);
                float2 kb = *(const float2*)(K1 + dc);
                float2 qb = *(const float2*)(Q1 + dc);
                float2 eaA = *(const float2*)&sA[rA0 + dc];
                float2 eaB = *(const float2*)&sA[rA1 + dc];

                float t00 = (ka.x + qa.x) * (c1[nt][0] + cw.x);
                float t01 = (ka.y + qa.y) * (c1[nt][1] + cw.y);
                float t10 = (kb.x + qb.x) * (c1[nt][2] + cw.x);
                float t11 = (kb.y + qb.y) * (c1[nt][3] + cw.y);
                float s00 = fmaxf(copysignf(sqrtf(fabsf(t00)), t00) + (c1[nt + 1][0] + cw.z), 0.f);
                float s01 = fmaxf(copysignf(sqrtf(fabsf(t01)), t01) + (c1[nt + 1][1] + cw.w), 0.f);
                float s10 = fmaxf(copysignf(sqrtf(fabsf(t10)), t10) + (c1[nt + 1][2] + cw.z), 0.f);
                float s11 = fmaxf(copysignf(sqrtf(fabsf(t11)), t11) + (c1[nt + 1][3] + cw.w), 0.f);

                unsigned pk0, pk1;
                asm("cvt.rn.bf16x2.f32 %0, %1, %2;" : "=r"(pk0) : "f"(s01), "f"(s00));
                asm("cvt.rn.bf16x2.f32 %0, %1, %2;" : "=r"(pk1) : "f"(s11), "f"(s10));
                d_sbufp[(size_t)e0 * 32 + h * 4 + tig] = pk0;
                d_sbufp[(size_t)e1 * 32 + h * 4 + tig] = pk1;

                if (nh == 0) {
                    sreg[hh][0] = s00; sreg[hh][1] = s01;
                    sreg[hh][2] = s10; sreg[hh][3] = s11;
                } else {
                    *(float2*)&sA[rA0 + dc] = make_float2(s00, s01);
                    *(float2*)&sA[rA1 + dc] = make_float2(s10, s11);
                }

                float p0 = s00 * cx.x + s01 * cx.y;
                float p1 = s10 * cx.x + s11 * cx.y;
                p0 += __shfl_xor_sync(FULLM, p0, 1);
                p0 += __shfl_xor_sync(FULLM, p0, 2);
                p1 += __shfl_xor_sync(FULLM, p1, 1);
                p1 += __shfl_xor_sync(FULLM, p1, 2);
                if (tig == 0) {
                    // store exp(clamp(score)) — node kernel consumes directly
                    d_scoreb[(size_t)e0 * 8 + h] = __expf(fminf(fmaxf(p0, -5.f), 5.f));
                    d_scoreb[(size_t)e1 * 8 + h] = __expf(fminf(fmaxf(p1, -5.f), 5.f));
                }

                c2[h][0] = eaA.x + cx.z; c2[h][1] = eaA.y + cx.w;
                c2[h][2] = eaB.x + cx.z; c2[h][3] = eaB.y + cx.w;
            }
        }

#pragma unroll
        for (int hh = 0; hh < 4; hh++) {
            const int dc = hh * 8 + 2 * tig;
            *(float2*)&sA[rA0 + dc] = make_float2(sreg[hh][0], sreg[hh][1]);
            *(float2*)&sA[rA1 + dc] = make_float2(sreg[hh][2], sreg[hh][3]);
        }
        __syncwarp();

#pragma unroll
        for (int p = 0; p < 4; p++) {
            int ka = 2 * p, kb = 2 * p + 1;
            unsigned a0 = cvt_tf32(sA[rA0 + ka * 8 + tig]);
            unsigned a1 = cvt_tf32(sA[rA1 + ka * 8 + tig]);
            unsigned a2 = cvt_tf32(sA[rA0 + ka * 8 + tig + 4]);
            unsigned a3 = cvt_tf32(sA[rA1 + ka * 8 + tig + 4]);
            unsigned a4 = cvt_tf32(sA[rA0 + kb * 8 + tig]);
            unsigned a5 = cvt_tf32(sA[rA1 + kb * 8 + tig]);
            unsigned a6 = cvt_tf32(sA[rA0 + kb * 8 + tig + 4]);
            unsigned a7 = cvt_tf32(sA[rA1 + kb * 8 + tig + 4]);
#pragma unroll
            for (int h = 0; h < 8; h++) {
                float4 bb = *(const float4*)
                    &sWOeT2[((h * 8 + g) * 4 + tig) * 20 + p * 4];
                MMA_TF32(c2[h], a0, a1, a2, a3, __float_as_uint(bb.x), __float_as_uint(bb.y));
                MMA_TF32(c2[h], a4, a5, a6, a7, __float_as_uint(bb.z), __float_as_uint(bb.w));
            }
        }

        __syncthreads();
        int next = tile + gridDim.x;
        if (next < NTILES) {
            prefetch_tile(sA, ea + (size_t)next * 8192, tid);
            asm volatile("cp.async.commit_group;");
        }

#pragma unroll
        for (int h = 0; h < 8; h++) {
            int wi = h * 4 + tig;
            int col = h * 8 + 2 * tig;
            float* cA = c2[h];
            d_eprh[(size_t)e0 * 32 + wi] = __floats2half2_rn(cA[0], cA[1]);
            d_eprh[(size_t)e1 * 32 + wi] = __floats2half2_rn(cA[2], cA[3]);
            float s0 = cA[0] + cA[2];
            float s1 = cA[1] + cA[3];
            float q0 = cA[0] * cA[0] + cA[2] * cA[2];
            float q1 = cA[1] * cA[1] + cA[3] * cA[3];
#pragma unroll
            for (int off = 4; off < 32; off <<= 1) {
                s0 += __shfl_xor_sync(FULLM, s0, off);
                s1 += __shfl_xor_sync(FULLM, s1, off);
                q0 += __shfl_xor_sync(FULLM, q0, off);
                q1 += __shfl_xor_sync(FULLM, q1, off);
            }
            if (l < 4) {
                atomicAdd(&sStats[col], s0);
                atomicAdd(&sStats[col + 1], s1);
                atomicAdd(&sStats[64 + col], q0);
                atomicAdd(&sStats[64 + col + 1], q1);
            }
        }
    }

    __syncthreads();
    if (tid < 64) {
        atomicAdd(&d_stats[tid], sStats[tid]);
        atomicAdd(&d_stats[64 + tid], sStats[64 + tid]);
    }
}

// ---------------- node gather (pair-lane mapping) + eout slice ----------------
__global__ void __launch_bounds__(256) k_node(const float* __restrict__ VeRow,
                                              const float* __restrict__ dcoef,
                                              const float* __restrict__ g1e,
                                              const float* __restrict__ b1e,
                                              float* __restrict__ eout) {
    __shared__ float seSc[64], seSh[64];
    int tid = threadIdx.x;
    if (tid < 64) {
        float mu = d_stats[tid] / NE;
        float var = d_stats[64 + tid] / NE - mu * mu;
        float sc = g1e[tid] * rsqrtf(var + 1e-5f);
        seSc[tid] = sc;
        seSh[tid] = b1e[tid] - mu * sc;
    }
    __syncthreads();

    int l = tid & 31;
    int n = blockIdx.x * 8 + (tid >> 5);
    if (n < NN) {
        int start = d_rowoff[n], end = d_rowoff[n + 1];
        int h = l >> 2;          // head for column pair (2l, 2l+1)
        float accV0 = 0.f, accV1 = 0.f, accR0 = 0.f, accR1 = 0.f, den = 0.f;
        for (int j = start; j < end; j += 32) {
            int m = end - j; if (m > 32) m = 32;
            int e_l = 0, s_l = 0;
            if (l < m) {
                e_l = __ldg(&d_col[j + l]);
                s_l = __ldg(&d_srcp[j + l]);
            }
#pragma unroll 2
            for (int t = 0; t < m; t++) {
                int e = __shfl_sync(FULLM, e_l, t);
                int src = __shfl_sync(FULLM, s_l, t);
                float ex = __ldg(&d_scoreb[(size_t)e * 8 + h]);   // already exp()
                den += ex;
                unsigned v = __ldg(&d_Vh[(size_t)src * 32 + l]);
                float2 vf = __half22float2(*(__half2*)&v);
                accV0 += vf.x * ex;
                accV1 += vf.y * ex;
                unsigned w = __ldg(&d_sbufp[(size_t)e * 32 + l]);
                accR0 += __uint_as_float(w << 16) * ex;
                accR1 += __uint_as_float(w & 0xffff0000u) * ex;
            }
        }
        float inv = 1.f / (den + 1e-16f);
        float rvx = accR0 * inv, rvy = accR1 * inv;
        float out0 = accV0 * inv, out1 = accV1 * inv;

        int qbase = l & ~3;
#pragma unroll
        for (int d = 0; d < 8; d++) {
            float rx = __shfl_sync(FULLM, rvx, qbase + (d >> 1));
            float ry = __shfl_sync(FULLM, rvy, qbase + (d >> 1));
            float rd = (d & 1) ? ry : rx;
            float2 vr = *(const float2*)&VeRow[d * 64 + 2 * l];
            out0 += rd * vr.x;
            out1 += rd * vr.y;
        }
        float deg = (float)(end - start);
        float ld = logf(deg + 1.f);
        float2 dc0 = *(const float2*)&dcoef[(2 * l) * 2];
        float2 dc1 = *(const float2*)&dcoef[(2 * l + 1) * 2];
        out0 *= (dc0.x + ld * dc0.y);
        out1 *= (dc1.x + ld * dc1.y);
        *(float2*)&d_hb[(size_t)n * 64 + 2 * l] = make_float2(out0, out1);
    }

    // ---- eout slice: 1024 uint4 per block ----
    {
        const __half2* eph = d_eprh;
        int base4 = blockIdx.x * 1024;
        for (int i = tid; i < 1024; i += 256) {
            int idx = base4 + i;
            int j0 = idx * 4;
            int cbase = (j0 & 31) * 2;
            float4 raw = __ldg((const float4*)(eph + j0));
            const __half2* hp = (const __half2*)&raw;
            float4 o0, o1;
            float2 v0 = __half22float2(hp[0]);
            float2 v1 = __half22float2(hp[1]);
            o0.x = v0.x * seSc[cbase + 0] + seSh[cbase + 0];
            o0.y = v0.y * seSc[cbase + 1] + seSh[cbase + 1];
            o0.z = v1.x * seSc[cbase + 2] + seSh[cbase + 2];
            o0.w = v1.y * seSc[cbase + 3] + seSh[cbase + 3];
            float2 v2 = __half22float2(hp[2]);
            float2 v3 = __half22float2(hp[3]);
            o1.x = v2.x * seSc[cbase + 4] + seSh[cbase + 4];
            o1.y = v2.y * seSc[cbase + 5] + seSh[cbase + 5];
            o1.z = v3.x * seSc[cbase + 6] + seSh[cbase + 6];
            o1.w = v3.y * seSc[cbase + 7] + seSh[cbase + 7];
            float4* op = (float4*)(eout + (size_t)j0 * 2);
            op[0] = o0;
            op[1] = o1;
        }
    }
}

// ---------------- t1 = x + hb @ WOh + bOh via MMA + BN1h stats ----------------
__global__ void __launch_bounds__(256) k_t1(const float* __restrict__ x,
                                            const float* __restrict__ WOh,
                                            const float* __restrict__ bOh) {
    extern __shared__ float sm[];
    float* sA = sm;
    float* sWT = sm + 8704;
    float* sStats = sm + 13312;
    int tid = threadIdx.x;
    if (tid < 128) sStats[tid] = 0.f;
    const int tileBase = blockIdx.x * 128;
    for (int i = tid; i < 8192; i += 256) {
        int r = i >> 6, c = i & 63;
        int n = tileBase + r;
        sA[r * 68 + c] = (n < NN) ? d_hb[(size_t)n * 64 + c] : 0.f;
    }
    for (int i = tid; i < 4096; i += 256) {
        int k = i >> 6, n = i & 63;
        int t7 = k & 7;
        int kd = (k & ~7) + ((t7 & 3) << 1) + (t7 >> 2);
        sWT[n * 72 + kd] = __uint_as_float(cvt_tf32(WOh[i]));
    }
    __syncthreads();

    const int l = tid & 31, w16 = (tid >> 5) * 16, g = l >> 2, tig = l & 3;
    const int rA0 = (w16 + g) * 68, rA1 = rA0 + 8 * 68;
    int n0 = tileBase + w16 + g, n1 = n0 + 8;
    bool v0r = n0 < NN, v1r = n1 < NN;

    float c[8][4];
#pragma unroll
    for (int nt = 0; nt < 8; nt++) {
        int col = nt * 8 + 2 * tig;
        float b0 = __ldg(&bOh[col]), b1 = __ldg(&bOh[col + 1]);
        float2 x0v = v0r ? *(const float2*)&x[(size_t)n0 * 64 + col] : make_float2(0.f, 0.f);
        float2 x1v = v1r ? *(const float2*)&x[(size_t)n1 * 64 + col] : make_float2(0.f, 0.f);
        c[nt][0] = b0 + x0v.x; c[nt][1] = b1 + x0v.y;
        c[nt][2] = b0 + x1v.x; c[nt][3] = b1 + x1v.y;
    }

#pragma unroll
    for (int ks = 0; ks < 8; ks++) {
        unsigned a0 = cvt_tf32(sA[rA0 + ks * 8 + tig]);
        unsigned a1 = cvt_tf32(sA[rA1 + ks * 8 + tig]);
        unsigned a2 = cvt_tf32(sA[rA0 + ks * 8 + tig + 4]);
        unsigned a3 = cvt_tf32(sA[rA1 + ks * 8 + tig + 4]);
#pragma unroll
        for (int nt = 0; nt < 8; nt++) {
            float2 bb = *(const float2*)&sWT[(nt * 8 + g) * 72 + ks * 8 + 2 * tig];
            MMA_TF32(c[nt], a0, a1, a2, a3, __float_as_uint(bb.x), __float_as_uint(bb.y));
        }
    }

#pragma unroll
    for (int nt = 0; nt < 8; nt++) {
        int col = nt * 8 + 2 * tig;
        if (v0r) *(float2*)&d_t1[(size_t)n0 * 64 + col] = make_float2(c[nt][0], c[nt][1]);
        if (v1r) *(float2*)&d_t1[(size_t)n1 * 64 + col] = make_float2(c[nt][2], c[nt][3]);
        float a0 = v0r ? c[nt][0] : 0.f, a1 = v0r ? c[nt][1] : 0.f;
        float a2 = v1r ? c[nt][2] : 0.f, a3 = v1r ? c[nt][3] : 0.f;
        float s0 = a0 + a2, s1 = a1 + a3;
        float q0 = a0 * a0 + a2 * a2, q1 = a1 * a1 + a3 * a3;
#pragma unroll
        for (int off = 4; off < 32; off <<= 1) {
            s0 += __shfl_xor_sync(FULLM, s0, off);
            s1 += __shfl_xor_sync(FULLM, s1, off);
            q0 += __shfl_xor_sync(FULLM, q0, off);
            q1 += __shfl_xor_sync(FULLM, q1, off);
        }
        if (l < 4) {
            atomicAdd(&sStats[col], s0);
            atomicAdd(&sStats[col + 1], s1);
            atomicAdd(&sStats[64 + col], q0);
            atomicAdd(&sStats[64 + col + 1], q1);
        }
    }
    __syncthreads();
    if (tid < 64) {
        atomicAdd(&d_stats[128 + tid], sStats[tid]);
        atomicAdd(&d_stats[192 + tid], sStats[64 + tid]);
    }
}

// ---------------- MLP via MMA ----------------
__global__ void __launch_bounds__(256) k_mlp(const float* __restrict__ g1h,
                                             const float* __restrict__ be1h,
                                             const float* __restrict__ W1,
                                             const float* __restrict__ b1v,
                                             const float* __restrict__ W2,
                                             const float* __restrict__ b2v) {
    extern __shared__ float sm[];
    float* sW2T = sm;
    float* sA   = sm + 8704;
    float* sW1T = sm + 17408;
    float* sMid = sm + 8704;
    float* sBNc = sm + 26624;
    float* sBNs = sm + 26688;
    float* sStats = sm + 26752;
    int tid = threadIdx.x;
    if (tid < 128) sStats[tid] = 0.f;
    if (tid < 64) {
        float mu = d_stats[128 + tid] / NN;
        float var = d_stats[192 + tid] / NN - mu * mu;
        float sc = g1h[tid] * rsqrtf(var + 1e-5f);
        sBNc[tid] = sc;
        sBNs[tid] = be1h[tid] - mu * sc;
    }
    for (int i = tid; i < 8192; i += 256) {
        int k = i >> 6, n = i & 63;
        int t7 = k & 7;
        int kd = (k & ~7) + ((t7 & 3) << 1) + (t7 >> 2);
        sW2T[n * 136 + kd] = __uint_as_float(cvt_tf32(W2[i]));
    }
    for (int i = tid; i < 8192; i += 256) {
        int k = i >> 7, n = i & 127;
        int t7 = k & 7;
        int kd = (k & ~7) + ((t7 & 3) << 1) + (t7 >> 2);
        sW1T[n * 72 + kd] = __uint_as_float(cvt_tf32(W1[i]));
    }
    __syncthreads();

    const int tileBase = blockIdx.x * 128;
    for (int i = tid; i < 8192; i += 256) {
        int r = i >> 6, c = i & 63;
        int n = tileBase + r;
        sA[r * 68 + c] = (n < NN) ? d_t1[(size_t)n * 64 + c] * sBNc[c] + sBNs[c] : 0.f;
    }
    __syncthreads();

    const int l = tid & 31, w16 = (tid >> 5) * 16, g = l >> 2, tig = l & 3;
    const int rA0 = (w16 + g) * 68, rA1 = rA0 + 8 * 68;

    float c1[16][4];
#pragma unroll
    for (int nt = 0; nt < 16; nt++) {
        int col = nt * 8 + 2 * tig;
        float b0 = __ldg(&b1v[col]), b1 = __ldg(&b1v[col + 1]);
        c1[nt][0] = b0; c1[nt][1] = b1; c1[nt][2] = b0; c1[nt][3] = b1;
    }
#pragma unroll
    for (int ks = 0; ks < 8; ks++) {
        unsigned a0 = cvt_tf32(sA[rA0 + ks * 8 + tig]);
        unsigned a1 = cvt_tf32(sA[rA1 + ks * 8 + tig]);
        unsigned a2 = cvt_tf32(sA[rA0 + ks * 8 + tig + 4]);
        unsigned a3 = cvt_tf32(sA[rA1 + ks * 8 + tig + 4]);
#pragma unroll
        for (int nt = 0; nt < 16; nt++) {
            float2 bb = *(const float2*)&sW1T[(nt * 8 + g) * 72 + ks * 8 + 2 * tig];
            MMA_TF32(c1[nt], a0, a1, a2, a3, __float_as_uint(bb.x), __float_as_uint(bb.y));
        }
    }

    float h1r[8][4];
#pragma unroll
    for (int nt = 0; nt < 8; nt++) {
        int col = nt * 8 + 2 * tig;
        float2 r0 = *(const float2*)&sA[rA0 + col];
        float2 r1 = *(const float2*)&sA[rA1 + col];
        h1r[nt][0] = r0.x; h1r[nt][1] = r0.y;
        h1r[nt][2] = r1.x; h1r[nt][3] = r1.y;
    }
    __syncthreads();

    const int rM0 = (w16 + g) * 132, rM1 = rM0 + 8 * 132;
#pragma unroll
    for (int nt = 0; nt < 16; nt++) {
        int col = nt * 8 + 2 * tig;
        *(float2*)&sMid[rM0 + col] = make_float2(fmaxf(c1[nt][0], 0.f), fmaxf(c1[nt][1], 0.f));
        *(float2*)&sMid[rM1 + col] = make_float2(fmaxf(c1[nt][2], 0.f), fmaxf(c1[nt][3], 0.f));
    }
    __syncthreads();

    float c2[8][4];
#pragma unroll
    for (int nt = 0; nt < 8; nt++) {
        int col = nt * 8 + 2 * tig;
        float b0 = __ldg(&b2v[col]), b1 = __ldg(&b2v[col + 1]);
        c2[nt][0] = h1r[nt][0] + b0; c2[nt][1] = h1r[nt][1] + b1;
        c2[nt][2] = h1r[nt][2] + b0; c2[nt][3] = h1r[nt][3] + b1;
    }
#pragma unroll
    for (int ks = 0; ks < 16; ks++) {
        unsigned a0 = cvt_tf32(sMid[rM0 + ks * 8 + tig]);
        unsigned a1 = cvt_tf32(sMid[rM1 + ks * 8 + tig]);
        unsigned a2 = cvt_tf32(sMid[rM0 + ks * 8 + tig + 4]);
        unsigned a3 = cvt_tf32(sMid[rM1 + ks * 8 + tig + 4]);
#pragma unroll
        for (int nt = 0; nt < 8; nt++) {
            float2 bb = *(const float2*)&sW2T[(nt * 8 + g) * 136 + ks * 8 + 2 * tig];
            MMA_TF32(c2[nt], a0, a1, a2, a3, __float_as_uint(bb.x), __float_as_uint(bb.y));
        }
    }

    int n0 = tileBase + w16 + g, n1 = n0 + 8;
    bool v0r = n0 < NN, v1r = n1 < NN;
#pragma unroll
    for (int nt = 0; nt < 8; nt++) {
        int col = nt * 8 + 2 * tig;
        if (v0r) *(float2*)&d_t2[(size_t)n0 * 64 + col] = make_float2(c2[nt][0], c2[nt][1]);
        if (v1r) *(float2*)&d_t2[(size_t)n1 * 64 + col] = make_float2(c2[nt][2], c2[nt][3]);
        float a0 = v0r ? c2[nt][0] : 0.f, a1 = v0r ? c2[nt][1] : 0.f;
        float a2 = v1r ? c2[nt][2] : 0.f, a3 = v1r ? c2[nt][3] : 0.f;
        float s0 = a0 + a2, s1 = a1 + a3;
        float q0 = a0 * a0 + a2 * a2, q1 = a1 * a1 + a3 * a3;
#pragma unroll
        for (int off = 4; off < 32; off <<= 1) {
            s0 += __shfl_xor_sync(FULLM, s0, off);
            s1 += __shfl_xor_sync(FULLM, s1, off);
            q0 += __shfl_xor_sync(FULLM, q0, off);
            q1 += __shfl_xor_sync(FULLM, q1, off);
        }
        if (l < 4) {
            atomicAdd(&sStats[col], s0);
            atomicAdd(&sStats[col + 1], s1);
            atomicAdd(&sStats[64 + col], q0);
            atomicAdd(&sStats[64 + col + 1], q1);
        }
    }
    __syncthreads();
    if (tid < 64) {
        atomicAdd(&d_stats[256 + tid], sStats[tid]);
        atomicAdd(&d_stats[320 + tid], sStats[64 + tid]);
    }
}

// ---------------- final h output ----------------
__global__ void k_hout(const float* __restrict__ g2h,
                       const float* __restrict__ b2h, float* __restrict__ out) {
    int idx0 = blockIdx.x * blockDim.x + threadIdx.x;
    int stride = gridDim.x * blockDim.x;
    int col = idx0 & 63;
    float mu = d_stats[256 + col] / NN;
    float var = d_stats[320 + col] / NN - mu * mu;
    float sc = g2h[col] * rsqrtf(var + 1e-5f);
    float sh = b2h[col] - mu * sc;
    for (int i = idx0; i < NN * 64; i += stride) out[i] = d_t2[i] * sc + sh;
}

// ---------------- launch ----------------
extern "C" void kernel_launch(void* const* d_in, const int* in_sizes, int n_in,
                              void* d_out, int out_size) {
    const float* x     = (const float*)d_in[0];
    const float* ea    = (const float*)d_in[1];
    const int*   eidx  = (const int*)d_in[2];
    const float* Wq    = (const float*)d_in[3];
    const float* bq    = (const float*)d_in[4];
    const float* Wk    = (const float*)d_in[5];
    const float* We    = (const float*)d_in[6];
    const float* be    = (const float*)d_in[7];
    const float* Wv    = (const float*)d_in[8];
    const float* Aw    = (const float*)d_in[9];
    const float* VeRow = (const float*)d_in[10];
    const float* dcoef = (const float*)d_in[11];
    const float* WOh   = (const float*)d_in[12];
    const float* bOh   = (const float*)d_in[13];
    const float* WOe   = (const float*)d_in[14];
    const float* bOe   = (const float*)d_in[15];
    const float* g1h   = (const float*)d_in[16];
    const float* b1h   = (const float*)d_in[17];
    const float* g1e   = (const float*)d_in[18];
    const float* b1e   = (const float*)d_in[19];
    const float* W1    = (const float*)d_in[20];
    const float* b1v   = (const float*)d_in[21];
    const float* W2    = (const float*)d_in[22];
    const float* b2v   = (const float*)d_in[23];
    const float* g2h   = (const float*)d_in[24];
    const float* b2h   = (const float*)d_in[25];
    float* out = (float*)d_out;

    const int edge_smem = 24448 * 4;   // 97,792 B -> 2 blocks/SM
    const int qkv_smem  = 22528 * 4;
    const int t1_smem   = 13440 * 4;
    const int mlp_smem  = 26880 * 4;
    cudaFuncSetAttribute(k_edge_mma, cudaFuncAttributeMaxDynamicSharedMemorySize, edge_smem);
    cudaFuncSetAttribute(k_qkv, cudaFuncAttributeMaxDynamicSharedMemorySize, qkv_smem);
    cudaFuncSetAttribute(k_t1, cudaFuncAttributeMaxDynamicSharedMemorySize, t1_smem);
    cudaFuncSetAttribute(k_mlp, cudaFuncAttributeMaxDynamicSharedMemorySize, mlp_smem);

    // k_edge_mma stays the 4th launch -> lands in the ncu capture slot.
    k_zero<<<196, 256>>>();
    k_qkv<<<NODE_TILES, 256, qkv_smem>>>(x, Wq, bq, Wk, Wv, eidx);
    k_scan<<<1, 1024>>>();
    k_edge_mma<<<296, 256, edge_smem>>>(ea, eidx, We, be, Aw, WOe, bOe);
    k_fill<<<3125, 256>>>(eidx);
    k_node<<<6250, 256>>>(VeRow, dcoef, g1e, b1e, out + (size_t)NN * 64);
    k_t1<<<NODE_TILES, 256, t1_smem>>>(x, WOh, bOh);
    k_mlp<<<NODE_TILES, 256, mlp_smem>>>(g1h, b1h, W1, b1v, W2, b2v);
    k_hout<<<512, 256>>>(g2h, b2h, out);
}

// round 17
// speedup vs baseline: 1.0668x; 1.0049x over previous
#include <cuda_runtime.h>
#include <cuda_fp16.h>
#include <math.h>

#define NN 50000
#define NE 800000
#define NTILES 6250
#define NODE_TILES 391
#define FULLM 0xffffffffu

// ---------------- device scratch ----------------
__device__ float    d_Q[NN * 64];
__device__ float    d_K[NN * 64];
__device__ unsigned d_Vh[NN * 32];      // fp16x2-packed V (cols 2i,2i+1)
__device__ float    d_hb[NN * 64];
__device__ unsigned d_sbufp[NE * 32];   // bf16x2-packed s, EDGE order
__device__ float    d_scoreb[NE * 8];   // EDGE order; stores exp(clamp(score))
__device__ __half2  d_eprh[NE * 32];    // fp16-packed epre (edge order)
__device__ float    d_t1[NN * 64];
__device__ float    d_t2[NN * 64];
__device__ int      d_rowoff[NN + 1];
__device__ int      d_counts[NN];
__device__ int      d_cursor[NN];
__device__ int      d_col[NE];
__device__ int      d_srcp[NE];
__device__ float    d_stats[384];

__device__ __forceinline__ unsigned cvt_tf32(float x) {
    unsigned r;
    asm("cvt.rna.tf32.f32 %0, %1;" : "=r"(r) : "f"(x));
    return r;
}

#define MMA_TF32(C, A0, A1, A2, A3, B0, B1)                                   \
    asm volatile(                                                             \
        "mma.sync.aligned.m16n8k8.row.col.f32.tf32.tf32.f32 "                 \
        "{%0,%1,%2,%3}, {%4,%5,%6,%7}, {%8,%9}, {%0,%1,%2,%3};"               \
        : "+f"(C[0]), "+f"(C[1]), "+f"(C[2]), "+f"(C[3])                      \
        : "r"(A0), "r"(A1), "r"(A2), "r"(A3), "r"(B0), "r"(B1))

// ---------------- zero ----------------
__global__ void k_zero() {
    int i = blockIdx.x * blockDim.x + threadIdx.x;
    if (i < NN) d_counts[i] = 0;
    if (i < 384) d_stats[i] = 0.f;
}

__global__ void k_scan() {
    __shared__ int sh[1024];
    int tid = threadIdx.x;
    const int per = (NN + 1023) / 1024;
    int s = tid * per;
    int e = s + per; if (e > NN) e = NN;
    int sum = 0;
    for (int i = s; i < e && i < NN; i++) sum += d_counts[i];
    sh[tid] = sum;
    __syncthreads();
    for (int off = 1; off < 1024; off <<= 1) {
        int t = (tid >= off) ? sh[tid - off] : 0;
        __syncthreads();
        sh[tid] += t;
        __syncthreads();
    }
    int run = sh[tid] - sum;
    for (int i = s; i < e && i < NN; i++) {
        d_rowoff[i] = run;
        d_cursor[i] = run;
        run += d_counts[i];
    }
    if (tid == 1023) d_rowoff[NN] = sh[1023];
}

__global__ void k_fill(const int* __restrict__ eidx) {
    int e = blockIdx.x * blockDim.x + threadIdx.x;
    if (e < NE) {
        int dst = eidx[NE + e];
        int p = atomicAdd(&d_cursor[dst], 1);
        d_col[p] = e;
        d_srcp[p] = eidx[e];
    }
}

// ---------------- Q,K,V via tf32 MMA (+ fused degree count) ----------------
__global__ void __launch_bounds__(256) k_qkv(const float* __restrict__ x,
                                             const float* __restrict__ Wq,
                                             const float* __restrict__ bq,
                                             const float* __restrict__ Wk,
                                             const float* __restrict__ Wv,
                                             const int* __restrict__ eidx) {
    extern __shared__ float sm[];
    float* sX  = sm;
    float* sWT = sm + 8704;
    int tid = threadIdx.x;

    for (int e = blockIdx.x * 256 + tid; e < NE; e += gridDim.x * 256)
        atomicAdd(&d_counts[eidx[NE + e]], 1);

    const int tileBase = blockIdx.x * 128;
    for (int i = tid; i < 8192; i += 256) {
        int r = i >> 6, c = i & 63;
        int n = tileBase + r;
        sX[r * 68 + c] = (n < NN) ? x[(size_t)n * 64 + c] : 0.f;
    }
    for (int i = tid; i < 4096; i += 256) {
        int k = i >> 6, n = i & 63;
        int t7 = k & 7;
        int kd = (k & ~7) + ((t7 & 3) << 1) + (t7 >> 2);
        sWT[n * 72 + kd]         = __uint_as_float(cvt_tf32(Wq[i]));
        sWT[(n + 64) * 72 + kd]  = __uint_as_float(cvt_tf32(Wk[i]));
        sWT[(n + 128) * 72 + kd] = __uint_as_float(cvt_tf32(Wv[i]));
    }
    __syncthreads();

    const int l = tid & 31, w16 = (tid >> 5) * 16, g = l >> 2, tig = l & 3;
    const int rA0 = (w16 + g) * 68, rA1 = rA0 + 8 * 68;

    float c[24][4];
#pragma unroll
    for (int nt = 0; nt < 24; nt++)
#pragma unroll
        for (int s = 0; s < 4; s++) c[nt][s] = 0.f;

#pragma unroll
    for (int ks = 0; ks < 8; ks++) {
        unsigned a0 = cvt_tf32(sX[rA0 + ks * 8 + tig]);
        unsigned a1 = cvt_tf32(sX[rA1 + ks * 8 + tig]);
        unsigned a2 = cvt_tf32(sX[rA0 + ks * 8 + tig + 4]);
        unsigned a3 = cvt_tf32(sX[rA1 + ks * 8 + tig + 4]);
#pragma unroll
        for (int nt = 0; nt < 24; nt++) {
            float2 bb = *(const float2*)&sWT[(nt * 8 + g) * 72 + ks * 8 + 2 * tig];
            MMA_TF32(c[nt], a0, a1, a2, a3, __float_as_uint(bb.x), __float_as_uint(bb.y));
        }
    }

    int n0 = tileBase + w16 + g, n1 = n0 + 8;
    bool v0r = n0 < NN, v1r = n1 < NN;
#pragma unroll
    for (int nt = 0; nt < 24; nt++) {
        int col = (nt & 7) * 8 + 2 * tig;
        if (nt < 8) {
            float b0 = __ldg(&bq[col]), b1 = __ldg(&bq[col + 1]);
            if (v0r) *(float2*)&d_Q[(size_t)n0 * 64 + col] = make_float2(c[nt][0] + b0, c[nt][1] + b1);
            if (v1r) *(float2*)&d_Q[(size_t)n1 * 64 + col] = make_float2(c[nt][2] + b0, c[nt][3] + b1);
        } else if (nt < 16) {
            if (v0r) *(float2*)&d_K[(size_t)n0 * 64 + col] = make_float2(c[nt][0], c[nt][1]);
            if (v1r) *(float2*)&d_K[(size_t)n1 * 64 + col] = make_float2(c[nt][2], c[nt][3]);
        } else {
            __half2 h0 = __floats2half2_rn(c[nt][0], c[nt][1]);
            __half2 h1 = __floats2half2_rn(c[nt][2], c[nt][3]);
            if (v0r) d_Vh[(size_t)n0 * 32 + (col >> 1)] = *(unsigned*)&h0;
            if (v1r) d_Vh[(size_t)n1 * 32 + (col >> 1)] = *(unsigned*)&h1;
        }
    }
}

// ---------------- persistent edge kernel: raw-tf32 A, stats externalized -----
// smem floats: sWeT2[10240]@0, sWOeT2[5120]@10240, sCst[256]@15360,
//              sA[128x68=8704]@15616 -> 24320 fl = 97,280 B (2 blocks/SM)
__device__ __forceinline__ void prefetch_tile(float* dst, const float* src, int tid) {
#pragma unroll
    for (int i = tid; i < 2048; i += 256) {
        int r = i >> 4, c4 = (i & 15) << 2;
        unsigned daddr = (unsigned)__cvta_generic_to_shared(dst + r * 68 + c4);
        asm volatile("cp.async.cg.shared.global [%0], [%1], 16;"
                     :: "r"(daddr), "l"(src + r * 64 + c4));
    }
}

__global__ void __launch_bounds__(256, 2) k_edge_mma(const float* __restrict__ ea,
                                                     const int* __restrict__ eidx,
                                                     const float* __restrict__ We,
                                                     const float* __restrict__ be,
                                                     const float* __restrict__ Aw,
                                                     const float* __restrict__ WOe,
                                                     const float* __restrict__ bOe) {
    extern __shared__ float smem[];
    float* sWeT2  = smem;
    float* sWOeT2 = smem + 10240;
    float* sCst   = smem + 15360;
    float* sA     = smem + 15616;

    const int tid = threadIdx.x;

    for (int i = tid; i < 8192; i += 256) {
        int k = i >> 7, n = i & 127;
        int nt = n >> 3, g2 = n & 7;
        int ks = k >> 3, t7 = k & 7;
        sWeT2[((nt * 8 + g2) * 4 + (t7 & 3)) * 20 + ks * 2 + (t7 >> 2)] =
            __uint_as_float(cvt_tf32(We[i]));
    }
    for (int i = tid; i < 4096; i += 256) {
        int k = i >> 6, n = i & 63;
        int nt = n >> 3, g2 = n & 7;
        int ks = k >> 3, t7 = k & 7;
        sWOeT2[((nt * 8 + g2) * 4 + (t7 & 3)) * 20 + ks * 2 + (t7 >> 2)] =
            __uint_as_float(cvt_tf32(WOe[i]));
    }
    if (tid < 32) {
        int h = tid >> 2, tg = tid & 3;
        sCst[tid * 4 + 0] = __ldg(&be[h * 16 + 2 * tg]);
        sCst[tid * 4 + 1] = __ldg(&be[h * 16 + 2 * tg + 1]);
        sCst[tid * 4 + 2] = __ldg(&be[h * 16 + 8 + 2 * tg]);
        sCst[tid * 4 + 3] = __ldg(&be[h * 16 + 9 + 2 * tg]);
        sCst[128 + tid * 4 + 0] = __ldg(&Aw[(2 * tg) * 8 + h]);
        sCst[128 + tid * 4 + 1] = __ldg(&Aw[(2 * tg + 1) * 8 + h]);
        sCst[128 + tid * 4 + 2] = __ldg(&bOe[h * 8 + 2 * tg]);
        sCst[128 + tid * 4 + 3] = __ldg(&bOe[h * 8 + 2 * tg + 1]);
    }

    const int l = tid & 31;
    const int w16 = (tid >> 5) * 16;
    const int g = l >> 2, tig = l & 3;
    const int rA0 = (w16 + g) * 68;
    const int rA1 = rA0 + 8 * 68;

    int tile = blockIdx.x;
    if (tile < NTILES) {
        prefetch_tile(sA, ea + (size_t)tile * 8192, tid);
        asm volatile("cp.async.commit_group;");
    }

    for (; tile < NTILES; tile += gridDim.x) {
        asm volatile("cp.async.wait_group 0;");
        __syncthreads();
        const int tileBase = tile * 128;

        const int e0 = tileBase + w16 + g;
        const int e1 = e0 + 8;
        int src0 = __ldg(&eidx[e0]), dst0 = __ldg(&eidx[NE + e0]);
        int src1 = __ldg(&eidx[e1]), dst1 = __ldg(&eidx[NE + e1]);
        const float* K0 = d_K + (size_t)src0 * 64;
        const float* Q0 = d_Q + (size_t)dst0 * 64;
        const float* K1 = d_K + (size_t)src1 * 64;
        const float* Q1 = d_Q + (size_t)dst1 * 64;

        float c2[8][4];
        float sreg[4][4];

#pragma unroll
        for (int nh = 0; nh < 2; nh++) {
            float c1[8][4];
#pragma unroll
            for (int nt = 0; nt < 8; nt++)
#pragma unroll
                for (int s = 0; s < 4; s++) c1[nt][s] = 0.f;

#pragma unroll
            for (int p = 0; p < 4; p++) {
                int ka = 2 * p, kb = 2 * p + 1;
                unsigned a0 = __float_as_uint(sA[rA0 + ka * 8 + tig]);
                unsigned a1 = __float_as_uint(sA[rA1 + ka * 8 + tig]);
                unsigned a2 = __float_as_uint(sA[rA0 + ka * 8 + tig + 4]);
                unsigned a3 = __float_as_uint(sA[rA1 + ka * 8 + tig + 4]);
                unsigned a4 = __float_as_uint(sA[rA0 + kb * 8 + tig]);
                unsigned a5 = __float_as_uint(sA[rA1 + kb * 8 + tig]);
                unsigned a6 = __float_as_uint(sA[rA0 + kb * 8 + tig + 4]);
                unsigned a7 = __float_as_uint(sA[rA1 + kb * 8 + tig + 4]);
#pragma unroll
                for (int nt = 0; nt < 8; nt++) {
                    float4 bb = *(const float4*)
                        &sWeT2[(((nh * 8 + nt) * 8 + g) * 4 + tig) * 20 + p * 4];
                    MMA_TF32(c1[nt], a0, a1, a2, a3, __float_as_uint(bb.x), __float_as_uint(bb.y));
                    MMA_TF32(c1[nt], a4, a5, a6, a7, __float_as_uint(bb.z), __float_as_uint(bb.w));
                }
            }

#pragma unroll
            for (int hh = 0; hh < 4; hh++) {
                const int h = nh * 4 + hh;
                const int nt = 2 * hh;
                const int dc = h * 8 + 2 * tig;
                float4 cw = *(const float4*)&sCst[(h * 4 + tig) * 4];
                float4 cx = *(const float4*)&sCst[128 + (h * 4 + tig) * 4];

                float2 ka = *(const float2*)(K0 + dc);
                float2 qa = *(const float2*)(Q0 + dc);
                float2 kb = *(const float2*)(K1 + dc);
                float2 qb = *(const float2*)(Q1 + dc);
                float2 eaA = *(const float2*)&sA[rA0 + dc];
                float2 eaB = *(const float2*)&sA[rA1 + dc];

                float t00 = (ka.x + qa.x) * (c1[nt][0] + cw.x);
                float t01 = (ka.y + qa.y) * (c1[nt][1] + cw.y);
                float t10 = (kb.x + qb.x) * (c1[nt][2] + cw.x);
                float t11 = (kb.y + qb.y) * (c1[nt][3] + cw.y);
                float s00 = fmaxf(copysignf(sqrtf(fabsf(t00)), t00) + (c1[nt + 1][0] + cw.z), 0.f);
                float s01 = fmaxf(copysignf(sqrtf(fabsf(t01)), t01) + (c1[nt + 1][1] + cw.w), 0.f);
                float s10 = fmaxf(copysignf(sqrtf(fabsf(t10)), t10) + (c1[nt + 1][2] + cw.z), 0.f);
                float s11 = fmaxf(copysignf(sqrtf(fabsf(t11)), t11) + (c1[nt + 1][3] + cw.w), 0.f);

                unsigned pk0, pk1;
                asm("cvt.rn.bf16x2.f32 %0, %1, %2;" : "=r"(pk0) : "f"(s01), "f"(s00));
                asm("cvt.rn.bf16x2.f32 %0, %1, %2;" : "=r"(pk1) : "f"(s11), "f"(s10));
                d_sbufp[(size_t)e0 * 32 + h * 4 + tig] = pk0;
                d_sbufp[(size_t)e1 * 32 + h * 4 + tig] = pk1;

                if (nh == 0) {
                    sreg[hh][0] = s00; sreg[hh][1] = s01;
                    sreg[hh][2] = s10; sreg[hh][3] = s11;
                } else {
                    *(float2*)&sA[rA0 + dc] = make_float2(s00, s01);
                    *(float2*)&sA[rA1 + dc] = make_float2(s10, s11);
                }

                float p0 = s00 * cx.x + s01 * cx.y;
                float p1 = s10 * cx.x + s11 * cx.y;
                p0 += __shfl_xor_sync(FULLM, p0, 1);
                p0 += __shfl_xor_sync(FULLM, p0, 2);
                p1 += __shfl_xor_sync(FULLM, p1, 1);
                p1 += __shfl_xor_sync(FULLM, p1, 2);
                if (tig == 0) {
                    d_scoreb[(size_t)e0 * 8 + h] = __expf(fminf(fmaxf(p0, -5.f), 5.f));
                    d_scoreb[(size_t)e1 * 8 + h] = __expf(fminf(fmaxf(p1, -5.f), 5.f));
                }

                c2[h][0] = eaA.x + cx.z; c2[h][1] = eaA.y + cx.w;
                c2[h][2] = eaB.x + cx.z; c2[h][3] = eaB.y + cx.w;
            }
        }

#pragma unroll
        for (int hh = 0; hh < 4; hh++) {
            const int dc = hh * 8 + 2 * tig;
            *(float2*)&sA[rA0 + dc] = make_float2(sreg[hh][0], sreg[hh][1]);
            *(float2*)&sA[rA1 + dc] = make_float2(sreg[hh][2], sreg[hh][3]);
        }
        __syncwarp();

#pragma unroll
        for (int p = 0; p < 4; p++) {
            int ka = 2 * p, kb = 2 * p + 1;
            unsigned a0 = __float_as_uint(sA[rA0 + ka * 8 + tig]);
            unsigned a1 = __float_as_uint(sA[rA1 + ka * 8 + tig]);
            unsigned a2 = __float_as_uint(sA[rA0 + ka * 8 + tig + 4]);
            unsigned a3 = __float_as_uint(sA[rA1 + ka * 8 + tig + 4]);
            unsigned a4 = __float_as_uint(sA[rA0 + kb * 8 + tig]);
            unsigned a5 = __float_as_uint(sA[rA1 + kb * 8 + tig]);
            unsigned a6 = __float_as_uint(sA[rA0 + kb * 8 + tig + 4]);
            unsigned a7 = __float_as_uint(sA[rA1 + kb * 8 + tig + 4]);
#pragma unroll
            for (int h = 0; h < 8; h++) {
                float4 bb = *(const float4*)
                    &sWOeT2[((h * 8 + g) * 4 + tig) * 20 + p * 4];
                MMA_TF32(c2[h], a0, a1, a2, a3, __float_as_uint(bb.x), __float_as_uint(bb.y));
                MMA_TF32(c2[h], a4, a5, a6, a7, __float_as_uint(bb.z), __float_as_uint(bb.w));
            }
        }

        __syncthreads();
        int next = tile + gridDim.x;
        if (next < NTILES) {
            prefetch_tile(sA, ea + (size_t)next * 8192, tid);
            asm volatile("cp.async.commit_group;");
        }

        // epilogue 2: just store epre (fp16); stats handled by k_estat
#pragma unroll
        for (int h = 0; h < 8; h++) {
            int wi = h * 4 + tig;
            d_eprh[(size_t)e0 * 32 + wi] = __floats2half2_rn(c2[h][0], c2[h][1]);
            d_eprh[(size_t)e1 * 32 + wi] = __floats2half2_rn(c2[h][2], c2[h][3]);
        }
    }
}

// ---------------- e-BN stats from fp16 epre ----------------
__global__ void __launch_bounds__(256) k_estat() {
    __shared__ float ss[128];
    int tid = threadIdx.x;
    if (tid < 128) ss[tid] = 0.f;
    __syncthreads();
    int h = tid & 7;                    // fixed float4-phase -> fixed 8 columns
    int r0 = blockIdx.x * 32 + (tid >> 3);
    int rstride = gridDim.x * 32;
    float s[8], q[8];
#pragma unroll
    for (int k = 0; k < 8; k++) { s[k] = 0.f; q[k] = 0.f; }
    const float4* base = (const float4*)d_eprh;   // NE rows x 8 float4
    for (int r = r0; r < NE; r += rstride) {
        float4 v = __ldg(&base[(size_t)r * 8 + h]);
        const __half2* hp = (const __half2*)&v;
#pragma unroll
        for (int k = 0; k < 4; k++) {
            float2 f = __half22float2(hp[k]);
            s[2 * k]     += f.x; q[2 * k]     += f.x * f.x;
            s[2 * k + 1] += f.y; q[2 * k + 1] += f.y * f.y;
        }
    }
#pragma unroll
    for (int k = 0; k < 8; k++) {
        atomicAdd(&ss[h * 8 + k], s[k]);
        atomicAdd(&ss[64 + h * 8 + k], q[k]);
    }
    __syncthreads();
    if (tid < 128) atomicAdd(&d_stats[tid], ss[tid]);
}

// ---------------- node gather (pair-lane mapping) + eout slice ----------------
__global__ void __launch_bounds__(256) k_node(const float* __restrict__ VeRow,
                                              const float* __restrict__ dcoef,
                                              const float* __restrict__ g1e,
                                              const float* __restrict__ b1e,
                                              float* __restrict__ eout) {
    __shared__ float seSc[64], seSh[64];
    int tid = threadIdx.x;
    if (tid < 64) {
        float mu = d_stats[tid] / NE;
        float var = d_stats[64 + tid] / NE - mu * mu;
        float sc = g1e[tid] * rsqrtf(var + 1e-5f);
        seSc[tid] = sc;
        seSh[tid] = b1e[tid] - mu * sc;
    }
    __syncthreads();

    int l = tid & 31;
    int n = blockIdx.x * 8 + (tid >> 5);
    if (n < NN) {
        int start = d_rowoff[n], end = d_rowoff[n + 1];
        int h = l >> 2;
        float accV0 = 0.f, accV1 = 0.f, accR0 = 0.f, accR1 = 0.f, den = 0.f;
        for (int j = start; j < end; j += 32) {
            int m = end - j; if (m > 32) m = 32;
            int e_l = 0, s_l = 0;
            if (l < m) {
                e_l = __ldg(&d_col[j + l]);
                s_l = __ldg(&d_srcp[j + l]);
            }
#pragma unroll 2
            for (int t = 0; t < m; t++) {
                int e = __shfl_sync(FULLM, e_l, t);
                int src = __shfl_sync(FULLM, s_l, t);
                float ex = __ldg(&d_scoreb[(size_t)e * 8 + h]);
                den += ex;
                unsigned v = __ldg(&d_Vh[(size_t)src * 32 + l]);
                float2 vf = __half22float2(*(__half2*)&v);
                accV0 += vf.x * ex;
                accV1 += vf.y * ex;
                unsigned w = __ldg(&d_sbufp[(size_t)e * 32 + l]);
                accR0 += __uint_as_float(w << 16) * ex;
                accR1 += __uint_as_float(w & 0xffff0000u) * ex;
            }
        }
        float inv = 1.f / (den + 1e-16f);
        float rvx = accR0 * inv, rvy = accR1 * inv;
        float out0 = accV0 * inv, out1 = accV1 * inv;

        int qbase = l & ~3;
#pragma unroll
        for (int d = 0; d < 8; d++) {
            float rx = __shfl_sync(FULLM, rvx, qbase + (d >> 1));
            float ry = __shfl_sync(FULLM, rvy, qbase + (d >> 1));
            float rd = (d & 1) ? ry : rx;
            float2 vr = *(const float2*)&VeRow[d * 64 + 2 * l];
            out0 += rd * vr.x;
            out1 += rd * vr.y;
        }
        float deg = (float)(end - start);
        float ld = logf(deg + 1.f);
        float2 dc0 = *(const float2*)&dcoef[(2 * l) * 2];
        float2 dc1 = *(const float2*)&dcoef[(2 * l + 1) * 2];
        out0 *= (dc0.x + ld * dc0.y);
        out1 *= (dc1.x + ld * dc1.y);
        *(float2*)&d_hb[(size_t)n * 64 + 2 * l] = make_float2(out0, out1);
    }

    // ---- eout slice ----
    {
        const __half2* eph = d_eprh;
        int base4 = blockIdx.x * 1024;
        for (int i = tid; i < 1024; i += 256) {
            int idx = base4 + i;
            int j0 = idx * 4;
            int cbase = (j0 & 31) * 2;
            float4 raw = __ldg((const float4*)(eph + j0));
            const __half2* hp = (const __half2*)&raw;
            float4 o0, o1;
            float2 v0 = __half22float2(hp[0]);
            float2 v1 = __half22float2(hp[1]);
            o0.x = v0.x * seSc[cbase + 0] + seSh[cbase + 0];
            o0.y = v0.y * seSc[cbase + 1] + seSh[cbase + 1];
            o0.z = v1.x * seSc[cbase + 2] + seSh[cbase + 2];
            o0.w = v1.y * seSc[cbase + 3] + seSh[cbase + 3];
            float2 v2 = __half22float2(hp[2]);
            float2 v3 = __half22float2(hp[3]);
            o1.x = v2.x * seSc[cbase + 4] + seSh[cbase + 4];
            o1.y = v2.y * seSc[cbase + 5] + seSh[cbase + 5];
            o1.z = v3.x * seSc[cbase + 6] + seSh[cbase + 6];
            o1.w = v3.y * seSc[cbase + 7] + seSh[cbase + 7];
            float4* op = (float4*)(eout + (size_t)j0 * 2);
            op[0] = o0;
            op[1] = o1;
        }
    }
}

// ---------------- t1 = x + hb @ WOh + bOh via MMA + BN1h stats ----------------
__global__ void __launch_bounds__(256) k_t1(const float* __restrict__ x,
                                            const float* __restrict__ WOh,
                                            const float* __restrict__ bOh) {
    extern __shared__ float sm[];
    float* sA = sm;
    float* sWT = sm + 8704;
    float* sStats = sm + 13312;
    int tid = threadIdx.x;
    if (tid < 128) sStats[tid] = 0.f;
    const int tileBase = blockIdx.x * 128;
    for (int i = tid; i < 8192; i += 256) {
        int r = i >> 6, c = i & 63;
        int n = tileBase + r;
        sA[r * 68 + c] = (n < NN) ? d_hb[(size_t)n * 64 + c] : 0.f;
    }
    for (int i = tid; i < 4096; i += 256) {
        int k = i >> 6, n = i & 63;
        int t7 = k & 7;
        int kd = (k & ~7) + ((t7 & 3) << 1) + (t7 >> 2);
        sWT[n * 72 + kd] = __uint_as_float(cvt_tf32(WOh[i]));
    }
    __syncthreads();

    const int l = tid & 31, w16 = (tid >> 5) * 16, g = l >> 2, tig = l & 3;
    const int rA0 = (w16 + g) * 68, rA1 = rA0 + 8 * 68;
    int n0 = tileBase + w16 + g, n1 = n0 + 8;
    bool v0r = n0 < NN, v1r = n1 < NN;

    float c[8][4];
#pragma unroll
    for (int nt = 0; nt < 8; nt++) {
        int col = nt * 8 + 2 * tig;
        float b0 = __ldg(&bOh[col]), b1 = __ldg(&bOh[col + 1]);
        float2 x0v = v0r ? *(const float2*)&x[(size_t)n0 * 64 + col] : make_float2(0.f, 0.f);
        float2 x1v = v1r ? *(const float2*)&x[(size_t)n1 * 64 + col] : make_float2(0.f, 0.f);
        c[nt][0] = b0 + x0v.x; c[nt][1] = b1 + x0v.y;
        c[nt][2] = b0 + x1v.x; c[nt][3] = b1 + x1v.y;
    }

#pragma unroll
    for (int ks = 0; ks < 8; ks++) {
        unsigned a0 = cvt_tf32(sA[rA0 + ks * 8 + tig]);
        unsigned a1 = cvt_tf32(sA[rA1 + ks * 8 + tig]);
        unsigned a2 = cvt_tf32(sA[rA0 + ks * 8 + tig + 4]);
        unsigned a3 = cvt_tf32(sA[rA1 + ks * 8 + tig + 4]);
#pragma unroll
        for (int nt = 0; nt < 8; nt++) {
            float2 bb = *(const float2*)&sWT[(nt * 8 + g) * 72 + ks * 8 + 2 * tig];
            MMA_TF32(c[nt], a0, a1, a2, a3, __float_as_uint(bb.x), __float_as_uint(bb.y));
        }
    }

#pragma unroll
    for (int nt = 0; nt < 8; nt++) {
        int col = nt * 8 + 2 * tig;
        if (v0r) *(float2*)&d_t1[(size_t)n0 * 64 + col] = make_float2(c[nt][0], c[nt][1]);
        if (v1r) *(float2*)&d_t1[(size_t)n1 * 64 + col] = make_float2(c[nt][2], c[nt][3]);
        float a0 = v0r ? c[nt][0] : 0.f, a1 = v0r ? c[nt][1] : 0.f;
        float a2 = v1r ? c[nt][2] : 0.f, a3 = v1r ? c[nt][3] : 0.f;
        float s0 = a0 + a2, s1 = a1 + a3;
        float q0 = a0 * a0 + a2 * a2, q1 = a1 * a1 + a3 * a3;
#pragma unroll
        for (int off = 4; off < 32; off <<= 1) {
            s0 += __shfl_xor_sync(FULLM, s0, off);
            s1 += __shfl_xor_sync(FULLM, s1, off);
            q0 += __shfl_xor_sync(FULLM, q0, off);
            q1 += __shfl_xor_sync(FULLM, q1, off);
        }
        if (l < 4) {
            atomicAdd(&sStats[col], s0);
            atomicAdd(&sStats[col + 1], s1);
            atomicAdd(&sStats[64 + col], q0);
            atomicAdd(&sStats[64 + col + 1], q1);
        }
    }
    __syncthreads();
    if (tid < 64) {
        atomicAdd(&d_stats[128 + tid], sStats[tid]);
        atomicAdd(&d_stats[192 + tid], sStats[64 + tid]);
    }
}

// ---------------- MLP via MMA ----------------
__global__ void __launch_bounds__(256) k_mlp(const float* __restrict__ g1h,
                                             const float* __restrict__ be1h,
                                             const float* __restrict__ W1,
                                             const float* __restrict__ b1v,
                                             const float* __restrict__ W2,
                                             const float* __restrict__ b2v) {
    extern __shared__ float sm[];
    float* sW2T = sm;
    float* sA   = sm + 8704;
    float* sW1T = sm + 17408;
    float* sMid = sm + 8704;
    float* sBNc = sm + 26624;
    float* sBNs = sm + 26688;
    float* sStats = sm + 26752;
    int tid = threadIdx.x;
    if (tid < 128) sStats[tid] = 0.f;
    if (tid < 64) {
        float mu = d_stats[128 + tid] / NN;
        float var = d_stats[192 + tid] / NN - mu * mu;
        float sc = g1h[tid] * rsqrtf(var + 1e-5f);
        sBNc[tid] = sc;
        sBNs[tid] = be1h[tid] - mu * sc;
    }
    for (int i = tid; i < 8192; i += 256) {
        int k = i >> 6, n = i & 63;
        int t7 = k & 7;
        int kd = (k & ~7) + ((t7 & 3) << 1) + (t7 >> 2);
        sW2T[n * 136 + kd] = __uint_as_float(cvt_tf32(W2[i]));
    }
    for (int i = tid; i < 8192; i += 256) {
        int k = i >> 7, n = i & 127;
        int t7 = k & 7;
        int kd = (k & ~7) + ((t7 & 3) << 1) + (t7 >> 2);
        sW1T[n * 72 + kd] = __uint_as_float(cvt_tf32(W1[i]));
    }
    __syncthreads();

    const int tileBase = blockIdx.x * 128;
    for (int i = tid; i < 8192; i += 256) {
        int r = i >> 6, c = i & 63;
        int n = tileBase + r;
        sA[r * 68 + c] = (n < NN) ? d_t1[(size_t)n * 64 + c] * sBNc[c] + sBNs[c] : 0.f;
    }
    __syncthreads();

    const int l = tid & 31, w16 = (tid >> 5) * 16, g = l >> 2, tig = l & 3;
    const int rA0 = (w16 + g) * 68, rA1 = rA0 + 8 * 68;

    float c1[16][4];
#pragma unroll
    for (int nt = 0; nt < 16; nt++) {
        int col = nt * 8 + 2 * tig;
        float b0 = __ldg(&b1v[col]), b1 = __ldg(&b1v[col + 1]);
        c1[nt][0] = b0; c1[nt][1] = b1; c1[nt][2] = b0; c1[nt][3] = b1;
    }
#pragma unroll
    for (int ks = 0; ks < 8; ks++) {
        unsigned a0 = cvt_tf32(sA[rA0 + ks * 8 + tig]);
        unsigned a1 = cvt_tf32(sA[rA1 + ks * 8 + tig]);
        unsigned a2 = cvt_tf32(sA[rA0 + ks * 8 + tig + 4]);
        unsigned a3 = cvt_tf32(sA[rA1 + ks * 8 + tig + 4]);
#pragma unroll
        for (int nt = 0; nt < 16; nt++) {
            float2 bb = *(const float2*)&sW1T[(nt * 8 + g) * 72 + ks * 8 + 2 * tig];
            MMA_TF32(c1[nt], a0, a1, a2, a3, __float_as_uint(bb.x), __float_as_uint(bb.y));
        }
    }

    float h1r[8][4];
#pragma unroll
    for (int nt = 0; nt < 8; nt++) {
        int col = nt * 8 + 2 * tig;
        float2 r0 = *(const float2*)&sA[rA0 + col];
        float2 r1 = *(const float2*)&sA[rA1 + col];
        h1r[nt][0] = r0.x; h1r[nt][1] = r0.y;
        h1r[nt][2] = r1.x; h1r[nt][3] = r1.y;
    }
    __syncthreads();

    const int rM0 = (w16 + g) * 132, rM1 = rM0 + 8 * 132;
#pragma unroll
    for (int nt = 0; nt < 16; nt++) {
        int col = nt * 8 + 2 * tig;
        *(float2*)&sMid[rM0 + col] = make_float2(fmaxf(c1[nt][0], 0.f), fmaxf(c1[nt][1], 0.f));
        *(float2*)&sMid[rM1 + col] = make_float2(fmaxf(c1[nt][2], 0.f), fmaxf(c1[nt][3], 0.f));
    }
    __syncthreads();

    float c2[8][4];
#pragma unroll
    for (int nt = 0; nt < 8; nt++) {
        int col = nt * 8 + 2 * tig;
        float b0 = __ldg(&b2v[col]), b1 = __ldg(&b2v[col + 1]);
        c2[nt][0] = h1r[nt][0] + b0; c2[nt][1] = h1r[nt][1] + b1;
        c2[nt][2] = h1r[nt][2] + b0; c2[nt][3] = h1r[nt][3] + b1;
    }
#pragma unroll
    for (int ks = 0; ks < 16; ks++) {
        unsigned a0 = cvt_tf32(sMid[rM0 + ks * 8 + tig]);
        unsigned a1 = cvt_tf32(sMid[rM1 + ks * 8 + tig]);
        unsigned a2 = cvt_tf32(sMid[rM0 + ks * 8 + tig + 4]);
        unsigned a3 = cvt_tf32(sMid[rM1 + ks * 8 + tig + 4]);
#pragma unroll
        for (int nt = 0; nt < 8; nt++) {
            float2 bb = *(const float2*)&sW2T[(nt * 8 + g) * 136 + ks * 8 + 2 * tig];
            MMA_TF32(c2[nt], a0, a1, a2, a3, __float_as_uint(bb.x), __float_as_uint(bb.y));
        }
    }

    int n0 = tileBase + w16 + g, n1 = n0 + 8;
    bool v0r = n0 < NN, v1r = n1 < NN;
#pragma unroll
    for (int nt = 0; nt < 8; nt++) {
        int col = nt * 8 + 2 * tig;
        if (v0r) *(float2*)&d_t2[(size_t)n0 * 64 + col] = make_float2(c2[nt][0], c2[nt][1]);
        if (v1r) *(float2*)&d_t2[(size_t)n1 * 64 + col] = make_float2(c2[nt][2], c2[nt][3]);
        float a0 = v0r ? c2[nt][0] : 0.f, a1 = v0r ? c2[nt][1] : 0.f;
        float a2 = v1r ? c2[nt][2] : 0.f, a3 = v1r ? c2[nt][3] : 0.f;
        float s0 = a0 + a2, s1 = a1 + a3;
        float q0 = a0 * a0 + a2 * a2, q1 = a1 * a1 + a3 * a3;
#pragma unroll
        for (int off = 4; off < 32; off <<= 1) {
            s0 += __shfl_xor_sync(FULLM, s0, off);
            s1 += __shfl_xor_sync(FULLM, s1, off);
            q0 += __shfl_xor_sync(FULLM, q0, off);
            q1 += __shfl_xor_sync(FULLM, q1, off);
        }
        if (l < 4) {
            atomicAdd(&sStats[col], s0);
            atomicAdd(&sStats[col + 1], s1);
            atomicAdd(&sStats[64 + col], q0);
            atomicAdd(&sStats[64 + col + 1], q1);
        }
    }
    __syncthreads();
    if (tid < 64) {
        atomicAdd(&d_stats[256 + tid], sStats[tid]);
        atomicAdd(&d_stats[320 + tid], sStats[64 + tid]);
    }
}

// ---------------- final h output ----------------
__global__ void k_hout(const float* __restrict__ g2h,
                       const float* __restrict__ b2h, float* __restrict__ out) {
    int idx0 = blockIdx.x * blockDim.x + threadIdx.x;
    int stride = gridDim.x * blockDim.x;
    int col = idx0 & 63;
    float mu = d_stats[256 + col] / NN;
    float var = d_stats[320 + col] / NN - mu * mu;
    float sc = g2h[col] * rsqrtf(var + 1e-5f);
    float sh = b2h[col] - mu * sc;
    for (int i = idx0; i < NN * 64; i += stride) out[i] = d_t2[i] * sc + sh;
}

// ---------------- launch ----------------
extern "C" void kernel_launch(void* const* d_in, const int* in_sizes, int n_in,
                              void* d_out, int out_size) {
    const float* x     = (const float*)d_in[0];
    const float* ea    = (const float*)d_in[1];
    const int*   eidx  = (const int*)d_in[2];
    const float* Wq    = (const float*)d_in[3];
    const float* bq    = (const float*)d_in[4];
    const float* Wk    = (const float*)d_in[5];
    const float* We    = (const float*)d_in[6];
    const float* be    = (const float*)d_in[7];
    const float* Wv    = (const float*)d_in[8];
    const float* Aw    = (const float*)d_in[9];
    const float* VeRow = (const float*)d_in[10];
    const float* dcoef = (const float*)d_in[11];
    const float* WOh   = (const float*)d_in[12];
    const float* bOh   = (const float*)d_in[13];
    const float* WOe   = (const float*)d_in[14];
    const float* bOe   = (const float*)d_in[15];
    const float* g1h   = (const float*)d_in[16];
    const float* b1h   = (const float*)d_in[17];
    const float* g1e   = (const float*)d_in[18];
    const float* b1e   = (const float*)d_in[19];
    const float* W1    = (const float*)d_in[20];
    const float* b1v   = (const float*)d_in[21];
    const float* W2    = (const float*)d_in[22];
    const float* b2v   = (const float*)d_in[23];
    const float* g2h   = (const float*)d_in[24];
    const float* b2h   = (const float*)d_in[25];
    float* out = (float*)d_out;

    const int edge_smem = 24320 * 4;   // 97,280 B -> 2 blocks/SM
    const int qkv_smem  = 22528 * 4;
    const int t1_smem   = 13440 * 4;
    const int mlp_smem  = 26880 * 4;
    cudaFuncSetAttribute(k_edge_mma, cudaFuncAttributeMaxDynamicSharedMemorySize, edge_smem);
    cudaFuncSetAttribute(k_qkv, cudaFuncAttributeMaxDynamicSharedMemorySize, qkv_smem);
    cudaFuncSetAttribute(k_t1, cudaFuncAttributeMaxDynamicSharedMemorySize, t1_smem);
    cudaFuncSetAttribute(k_mlp, cudaFuncAttributeMaxDynamicSharedMemorySize, mlp_smem);

    // k_edge_mma stays the 4th launch -> lands in the ncu capture slot.
    k_zero<<<196, 256>>>();
    k_qkv<<<NODE_TILES, 256, qkv_smem>>>(x, Wq, bq, Wk, Wv, eidx);
    k_scan<<<1, 1024>>>();
    k_edge_mma<<<296, 256, edge_smem>>>(ea, eidx, We, be, Aw, WOe, bOe);
    k_fill<<<3125, 256>>>(eidx);
    k_estat<<<592, 256>>>();
    k_node<<<6250, 256>>>(VeRow, dcoef, g1e, b1e, out + (size_t)NN * 64);
    k_t1<<<NODE_TILES, 256, t1_smem>>>(x, WOh, bOh);
    k_mlp<<<NODE_TILES, 256, mlp_smem>>>(g1h, b1h, W1, b1v, W2, b2v);
    k_hout<<<512, 256>>>(g2h, b2h, out);
}